// round 1
// baseline (speedup 1.0000x reference)
#include <cuda_runtime.h>
#include <cuda_bf16.h>
#include <math.h>

// ---------------- problem constants ----------------
#define BATCH   2
#define CMODEL  96
#define HH      64
#define WW      64
#define LSEQ    4096            // 64*64
#define BB      8               // BATCH*4 directions
#define DIN     192             // D_INNER
#define DSTATE  128
#define CONVD   448             // DIN + 2*DSTATE
#define NH      3
#define HD      64
#define NPROJ   643             // 2*DIN + 2*DSTATE + NH
#define CHUNK   256
#define NC      16
#define MROWS   (BB*LSEQ)       // 32768

// ---------------- scratch (device globals; no allocation allowed) ----------------
__device__ float g_xs[MROWS * CMODEL];          // cross-scanned normed input
__device__ float g_zxbcdt[MROWS * NPROJ];       // in_proj output
__device__ float g_xBC[MROWS * CONVD];          // post conv+silu
__device__ float g_dt[MROWS * NH];
__device__ float g_dAc[MROWS * NH];             // per-chunk inclusive cumsum of dt*A
__device__ float g_y[MROWS * DIN];
__device__ float g_yn[MROWS * DIN];
__device__ float g_ysd[MROWS * CMODEL];         // out_proj result
__device__ float g_states[BB * NC * NH * HD * DSTATE];
__device__ float g_prev[BB * NC * NH * HD * DSTATE];

// ============ kernel 1: per-pixel rmsnorm + cross-scan scatter ============
__global__ void k_rms_scan(const float* __restrict__ x, const float* __restrict__ norm_w) {
    int bx = blockIdx.x;
    int bi = bx >> 12;
    int l  = bx & 4095;
    int ch = threadIdx.x;                 // 96 threads
    float v = x[((bi * CMODEL + ch) << 12) + l];
    float ss = v * v;
    #pragma unroll
    for (int o = 16; o > 0; o >>= 1) ss += __shfl_down_sync(0xffffffffu, ss, o);
    __shared__ float sred[3];
    __shared__ float stot;
    int wid = ch >> 5, lane = ch & 31;
    if (lane == 0) sred[wid] = ss;
    __syncthreads();
    if (ch == 0) stot = sred[0] + sred[1] + sred[2];
    __syncthreads();
    float nv = v * rsqrtf(stot / 96.0f + 1.1920929e-07f) * norm_w[ch];
    int hh = l >> 6, ww = l & 63;
    int lt = (ww << 6) + hh;
    g_xs[((((bi * 4 + 0) << 12) + l) * CMODEL) + ch] = nv;
    g_xs[((((bi * 4 + 1) << 12) + (4095 - l)) * CMODEL) + ch] = nv;
    g_xs[((((bi * 4 + 2) << 12) + lt) * CMODEL) + ch] = nv;
    g_xs[((((bi * 4 + 3) << 12) + (4095 - lt)) * CMODEL) + ch] = nv;
}

// ============ kernel 2: in_proj GEMM  (M=32768, N=643, K=96) ============
// C[m][n] = sum_k xs[m][k] * W[n][k]
__global__ void k_inproj(const float* __restrict__ W) {
    __shared__ float As[64][33];
    __shared__ float Bs[64][33];
    int bm = blockIdx.y * 64;
    int bn = blockIdx.x * 64;
    int tx = threadIdx.x, ty = threadIdx.y, tid = ty * 16 + tx;
    float acc[4][4] = {};
    for (int kk = 0; kk < 96; kk += 32) {
        for (int i = tid; i < 64 * 32; i += 256) {
            int r = i >> 5, k = i & 31;
            As[r][k] = g_xs[(bm + r) * CMODEL + kk + k];
        }
        for (int i = tid; i < 64 * 32; i += 256) {
            int r = i >> 5, k = i & 31;
            int n = bn + r;
            Bs[r][k] = (n < NPROJ) ? W[n * CMODEL + kk + k] : 0.0f;
        }
        __syncthreads();
        #pragma unroll
        for (int k = 0; k < 32; k++) {
            float a[4], b[4];
            #pragma unroll
            for (int i = 0; i < 4; i++) a[i] = As[ty + 16 * i][k];
            #pragma unroll
            for (int j = 0; j < 4; j++) b[j] = Bs[tx + 16 * j][k];
            #pragma unroll
            for (int i = 0; i < 4; i++)
                #pragma unroll
                for (int j = 0; j < 4; j++) acc[i][j] = fmaf(a[i], b[j], acc[i][j]);
        }
        __syncthreads();
    }
    #pragma unroll
    for (int i = 0; i < 4; i++) {
        int row = bm + ty + 16 * i;
        #pragma unroll
        for (int j = 0; j < 4; j++) {
            int col = bn + tx + 16 * j;
            if (col < NPROJ) g_zxbcdt[row * NPROJ + col] = acc[i][j];
        }
    }
}

// ============ kernel 3: dt = softplus(raw + bias);  dAc = per-chunk cumsum(dt*A) ============
__global__ void k_dt(const float* __restrict__ dt_bias, const float* __restrict__ A_log) {
    int cb = blockIdx.x;          // bb*16 + chunk  (128 blocks)
    int t  = threadIdx.x;         // 256
    int m  = cb * CHUNK + t;
    __shared__ float sc[256];
    for (int h = 0; h < NH; h++) {
        float raw = g_zxbcdt[m * NPROJ + (DIN + CONVD) + h] + dt_bias[h];
        float dtv = (raw > 20.0f) ? raw : log1pf(expf(raw));
        g_dt[m * NH + h] = dtv;
        float Ah = -expf(A_log[h]);
        sc[t] = dtv * Ah;
        __syncthreads();
        for (int off = 1; off < 256; off <<= 1) {
            float tmp = (t >= off) ? sc[t - off] : 0.0f;
            __syncthreads();
            sc[t] += tmp;
            __syncthreads();
        }
        g_dAc[m * NH + h] = sc[t];
        __syncthreads();
    }
}

// ============ kernel 4: depthwise causal conv (k=4) + SiLU ============
__global__ void k_conv(const float* __restrict__ cw, const float* __restrict__ cb) {
    int m = blockIdx.x;
    int t = m & 4095;
    int ch = threadIdx.x;         // 448
    float acc = cb[ch];
    #pragma unroll
    for (int i = 0; i < 4; i++) {
        int tt = t - 3 + i;
        if (tt >= 0) acc = fmaf(cw[ch * 4 + i], g_zxbcdt[(m - 3 + i) * NPROJ + DIN + ch], acc);
    }
    g_xBC[m * CONVD + ch] = acc / (1.0f + expf(-acc));
}

// ============ kernel 5: intra-chunk SSD  (chained GEMM with segsum scaling) ============
// one block: (bb, chunk, head, s_tile of 64 rows); Y[64s x 64p]
__global__ void k_intra() {
    int bx = blockIdx.x;
    int st = bx & 3;
    int rest = bx >> 2;
    int h = rest % 3; rest /= 3;
    int c = rest & 15;
    int bb = rest >> 4;
    int m0 = bb * LSEQ + c * CHUNK;

    __shared__ float Cs[64][17], Bs[64][17], Xs[64][65], Ssm[64][65];
    __shared__ float dAs[64], dAt[64], dtt[64];
    int tx = threadIdx.x, ty = threadIdx.y, tid = ty * 16 + tx;

    if (tid < 64) dAs[tid] = g_dAc[(m0 + st * 64 + tid) * NH + h];
    float acc[4][4] = {};
    __syncthreads();

    for (int tt = 0; tt <= st; tt++) {
        int tbase = m0 + tt * 64;
        if (tid < 64) {
            dAt[tid] = g_dAc[(tbase + tid) * NH + h];
            dtt[tid] = g_dt[(tbase + tid) * NH + h];
        }
        for (int i = tid; i < 64 * 64; i += 256) {
            int r = i >> 6, p = i & 63;
            Xs[r][p] = g_xBC[(tbase + r) * CONVD + h * HD + p];
        }
        float S[4][4] = {};
        for (int kk = 0; kk < 128; kk += 16) {
            for (int i = tid; i < 64 * 16; i += 256) {
                int r = i >> 4, k = i & 15;
                Cs[r][k] = g_xBC[(m0 + st * 64 + r) * CONVD + (DIN + DSTATE) + kk + k];
            }
            for (int i = tid; i < 64 * 16; i += 256) {
                int r = i >> 4, k = i & 15;
                Bs[r][k] = g_xBC[(tbase + r) * CONVD + DIN + kk + k];
            }
            __syncthreads();
            #pragma unroll
            for (int k = 0; k < 16; k++) {
                float a[4], b[4];
                #pragma unroll
                for (int i = 0; i < 4; i++) a[i] = Cs[ty + 16 * i][k];
                #pragma unroll
                for (int j = 0; j < 4; j++) b[j] = Bs[tx + 16 * j][k];
                #pragma unroll
                for (int i = 0; i < 4; i++)
                    #pragma unroll
                    for (int j = 0; j < 4; j++) S[i][j] = fmaf(a[i], b[j], S[i][j]);
            }
            __syncthreads();
        }
        // scale by exp(dA[s]-dA[t]) * dt[t], causal mask on diagonal tile
        #pragma unroll
        for (int i = 0; i < 4; i++) {
            int sl = ty + 16 * i;
            #pragma unroll
            for (int j = 0; j < 4; j++) {
                int tl = tx + 16 * j;
                bool ok = (tt < st) || (tl <= sl);
                float f = ok ? expf(dAs[sl] - dAt[tl]) * dtt[tl] : 0.0f;
                Ssm[sl][tl] = S[i][j] * f;
            }
        }
        __syncthreads();
        #pragma unroll
        for (int k = 0; k < 64; k++) {
            float a[4], b[4];
            #pragma unroll
            for (int i = 0; i < 4; i++) a[i] = Ssm[ty + 16 * i][k];
            #pragma unroll
            for (int j = 0; j < 4; j++) b[j] = Xs[k][tx + 16 * j];
            #pragma unroll
            for (int i = 0; i < 4; i++)
                #pragma unroll
                for (int j = 0; j < 4; j++) acc[i][j] = fmaf(a[i], b[j], acc[i][j]);
        }
        __syncthreads();
    }
    #pragma unroll
    for (int i = 0; i < 4; i++) {
        int s = st * 64 + ty + 16 * i;
        #pragma unroll
        for (int j = 0; j < 4; j++) {
            int p = tx + 16 * j;
            g_y[(m0 + s) * DIN + h * HD + p] = acc[i][j];
        }
    }
}

// ============ kernel 6: per-chunk end states  states[p][n] = sum_t wt[t]*B[t][n]*x[t][p] ============
__global__ void k_states() {
    int bx = blockIdx.x;            // 384 = bb*16*3
    int h = bx % 3; int rest = bx / 3;
    int c = rest & 15; int bb = rest >> 4;
    int m0 = bb * LSEQ + c * CHUNK;
    __shared__ float Xh[32][65], Bw[32][129], wts[32];
    int tx = threadIdx.x, ty = threadIdx.y, tid = ty * 16 + tx;
    float dAl = g_dAc[(m0 + 255) * NH + h];
    float acc[4][8] = {};
    for (int tc = 0; tc < CHUNK; tc += 32) {
        if (tid < 32) {
            int t = tc + tid;
            wts[tid] = expf(dAl - g_dAc[(m0 + t) * NH + h]) * g_dt[(m0 + t) * NH + h];
        }
        __syncthreads();
        for (int i = tid; i < 32 * 64; i += 256) {
            int r = i >> 6, p = i & 63;
            Xh[r][p] = g_xBC[(m0 + tc + r) * CONVD + h * HD + p];
        }
        for (int i = tid; i < 32 * 128; i += 256) {
            int r = i >> 7, n = i & 127;
            Bw[r][n] = wts[r] * g_xBC[(m0 + tc + r) * CONVD + DIN + n];
        }
        __syncthreads();
        #pragma unroll
        for (int t = 0; t < 32; t++) {
            float a[4], b[8];
            #pragma unroll
            for (int i = 0; i < 4; i++) a[i] = Xh[t][ty + 16 * i];
            #pragma unroll
            for (int j = 0; j < 8; j++) b[j] = Bw[t][tx + 16 * j];
            #pragma unroll
            for (int i = 0; i < 4; i++)
                #pragma unroll
                for (int j = 0; j < 8; j++) acc[i][j] = fmaf(a[i], b[j], acc[i][j]);
        }
        __syncthreads();
    }
    int blk = (bb * 16 + c) * 3 + h;
    #pragma unroll
    for (int i = 0; i < 4; i++) {
        int p = ty + 16 * i;
        #pragma unroll
        for (int j = 0; j < 8; j++) {
            int n = tx + 16 * j;
            g_states[blk * (HD * DSTATE) + p * DSTATE + n] = acc[i][j];
        }
    }
}

// ============ kernel 7: inter-chunk recurrence (sequential over 16 chunks) ============
__global__ void k_recur() {
    int bb = blockIdx.x / 3, h = blockIdx.x % 3;
    int tid = threadIdx.x;          // 256
    float hr[32];
    #pragma unroll
    for (int r = 0; r < 32; r++) hr[r] = 0.0f;
    for (int c = 0; c < NC; c++) {
        int blk = (bb * 16 + c) * 3 + h;
        float decay = expf(g_dAc[(bb * LSEQ + c * CHUNK + 255) * NH + h]);
        #pragma unroll
        for (int r = 0; r < 32; r++) {
            int idx = blk * (HD * DSTATE) + r * 256 + tid;
            g_prev[idx] = hr[r];
            hr[r] = fmaf(decay, hr[r], g_states[idx]);
        }
    }
}

// ============ kernel 8: inter-chunk y correction + D*x ============
// y[s][p] += exp(dAc[s]) * sum_n C[s][n]*prev[p][n]  +  D[h]*x[s][p]
__global__ void k_ycorr(const float* __restrict__ Dp) {
    int bx = blockIdx.x;            // 384
    int h = bx % 3; int rest = bx / 3;
    int c = rest & 15; int bb = rest >> 4;
    int m0 = bb * LSEQ + c * CHUNK;
    int blk = (bb * 16 + c) * 3 + h;
    __shared__ float prevS[64][129];
    __shared__ float Cs[64][33];
    int tx = threadIdx.x, ty = threadIdx.y, tid = ty * 16 + tx;
    for (int i = tid; i < HD * DSTATE; i += 256) {
        int p = i >> 7, n = i & 127;
        prevS[p][n] = g_prev[blk * (HD * DSTATE) + i];
    }
    float Dh = Dp[h];
    for (int stile = 0; stile < 4; stile++) {
        float acc[4][4] = {};
        for (int kk = 0; kk < 128; kk += 32) {
            for (int i = tid; i < 64 * 32; i += 256) {
                int r = i >> 5, k = i & 31;
                Cs[r][k] = g_xBC[(m0 + stile * 64 + r) * CONVD + (DIN + DSTATE) + kk + k];
            }
            __syncthreads();
            #pragma unroll
            for (int k = 0; k < 32; k++) {
                float a[4], b[4];
                #pragma unroll
                for (int i = 0; i < 4; i++) a[i] = Cs[ty + 16 * i][k];
                #pragma unroll
                for (int j = 0; j < 4; j++) b[j] = prevS[tx + 16 * j][kk + k];
                #pragma unroll
                for (int i = 0; i < 4; i++)
                    #pragma unroll
                    for (int j = 0; j < 4; j++) acc[i][j] = fmaf(a[i], b[j], acc[i][j]);
            }
            __syncthreads();
        }
        #pragma unroll
        for (int i = 0; i < 4; i++) {
            int s = stile * 64 + ty + 16 * i;
            int m = m0 + s;
            float eA = expf(g_dAc[m * NH + h]);
            #pragma unroll
            for (int j = 0; j < 4; j++) {
                int p = tx + 16 * j;
                float xv = g_xBC[m * CONVD + h * HD + p];
                g_y[m * DIN + h * HD + p] += eA * acc[i][j] + Dh * xv;
            }
        }
    }
}

// ============ kernel 9: gating with silu(z) + rmsnorm(gnorm_w, eps=1e-5) ============
__global__ void k_gate(const float* __restrict__ gw) {
    int m = blockIdx.x;
    int d = threadIdx.x;            // 192
    float y = g_y[m * DIN + d];
    float z = g_zxbcdt[m * NPROJ + d];
    float v = y * (z / (1.0f + expf(-z)));
    float ss = v * v;
    #pragma unroll
    for (int o = 16; o > 0; o >>= 1) ss += __shfl_down_sync(0xffffffffu, ss, o);
    __shared__ float sred[6];
    __shared__ float stot;
    int wid = d >> 5, lane = d & 31;
    if (lane == 0) sred[wid] = ss;
    __syncthreads();
    if (d == 0) stot = sred[0] + sred[1] + sred[2] + sred[3] + sred[4] + sred[5];
    __syncthreads();
    g_yn[m * DIN + d] = v * rsqrtf(stot / 192.0f + 1e-5f) * gw[d];
}

// ============ kernel 10: out_proj GEMM (M=32768, N=96, K=192) ============
__global__ void k_outproj(const float* __restrict__ W) {
    __shared__ float As[64][33];
    __shared__ float Bs[96][33];
    int bm = blockIdx.x * 64;
    int tx = threadIdx.x, ty = threadIdx.y, tid = ty * 16 + tx;
    float acc[4][6] = {};
    for (int kk = 0; kk < 192; kk += 32) {
        for (int i = tid; i < 64 * 32; i += 256) {
            int r = i >> 5, k = i & 31;
            As[r][k] = g_yn[(bm + r) * DIN + kk + k];
        }
        for (int i = tid; i < 96 * 32; i += 256) {
            int r = i >> 5, k = i & 31;
            Bs[r][k] = W[r * DIN + kk + k];
        }
        __syncthreads();
        #pragma unroll
        for (int k = 0; k < 32; k++) {
            float a[4], b[6];
            #pragma unroll
            for (int i = 0; i < 4; i++) a[i] = As[ty + 16 * i][k];
            #pragma unroll
            for (int j = 0; j < 6; j++) b[j] = Bs[tx + 16 * j][k];
            #pragma unroll
            for (int i = 0; i < 4; i++)
                #pragma unroll
                for (int j = 0; j < 6; j++) acc[i][j] = fmaf(a[i], b[j], acc[i][j]);
        }
        __syncthreads();
    }
    #pragma unroll
    for (int i = 0; i < 4; i++) {
        int row = bm + ty + 16 * i;
        #pragma unroll
        for (int j = 0; j < 6; j++) {
            g_ysd[row * CMODEL + tx + 16 * j] = acc[i][j];
        }
    }
}

// ============ kernel 11: un-scan (gather 4 directions, average) + residual ============
__global__ void k_unscan(const float* __restrict__ x, float* __restrict__ out) {
    int bx = blockIdx.x;
    int bi = bx >> 12;
    int l  = bx & 4095;
    int ch = threadIdx.x;           // 96
    int hh = l >> 6, ww = l & 63;
    int lt = (ww << 6) + hh;
    float v = g_ysd[((((bi * 4 + 0) << 12) + l) * CMODEL) + ch]
            + g_ysd[((((bi * 4 + 1) << 12) + (4095 - l)) * CMODEL) + ch]
            + g_ysd[((((bi * 4 + 2) << 12) + lt) * CMODEL) + ch]
            + g_ysd[((((bi * 4 + 3) << 12) + (4095 - lt)) * CMODEL) + ch];
    int idx = ((bi * CMODEL + ch) << 12) + l;
    out[idx] = x[idx] + 0.25f * v;
}

// ---------------- launch ----------------
extern "C" void kernel_launch(void* const* d_in, const int* in_sizes, int n_in,
                              void* d_out, int out_size) {
    const float* x          = (const float*)d_in[0];
    const float* norm_w     = (const float*)d_in[1];
    const float* in_proj_w  = (const float*)d_in[2];
    const float* conv_w     = (const float*)d_in[3];
    const float* conv_b     = (const float*)d_in[4];
    const float* dt_bias    = (const float*)d_in[5];
    const float* A_log      = (const float*)d_in[6];
    const float* Dp         = (const float*)d_in[7];
    const float* gnorm_w    = (const float*)d_in[8];
    const float* out_proj_w = (const float*)d_in[9];
    float* out = (float*)d_out;

    dim3 t16(16, 16);

    k_rms_scan<<<BATCH * LSEQ, CMODEL>>>(x, norm_w);
    k_inproj<<<dim3((NPROJ + 63) / 64, MROWS / 64), t16>>>(in_proj_w);
    k_dt<<<BB * NC, CHUNK>>>(dt_bias, A_log);
    k_conv<<<MROWS, CONVD>>>(conv_w, conv_b);
    k_intra<<<BB * NC * NH * 4, t16>>>();
    k_states<<<BB * NC * NH, t16>>>();
    k_recur<<<BB * NH, 256>>>();
    k_ycorr<<<BB * NC * NH, t16>>>(Dp);
    k_gate<<<MROWS, DIN>>>(gnorm_w);
    k_outproj<<<MROWS / 64, t16>>>(out_proj_w);
    k_unscan<<<BATCH * LSEQ, CMODEL>>>(x, out);
}

// round 2
// speedup vs baseline: 1.3075x; 1.3075x over previous
#include <cuda_runtime.h>
#include <cuda_bf16.h>
#include <math.h>
#include <stdint.h>

// ---------------- problem constants ----------------
#define BATCH   2
#define CMODEL  96
#define LSEQ    4096            // 64*64
#define BB      8               // BATCH*4 directions
#define DIN     192             // D_INNER
#define DSTATE  128
#define CONVD   448             // DIN + 2*DSTATE
#define NH      3
#define HD      64
#define NPROJ   643             // 2*DIN + 2*DSTATE + NH
#define CHUNK   256
#define NC      16
#define MROWS   (BB*LSEQ)       // 32768

// ---------------- scratch ----------------
__device__ float g_xs[MROWS * CMODEL];
__device__ float g_zxbcdt[MROWS * NPROJ];
__device__ float g_xBC[MROWS * CONVD];
__device__ float g_dt[MROWS * NH];
__device__ float g_dAc[MROWS * NH];
__device__ float g_y[MROWS * DIN];
__device__ float g_yn[MROWS * DIN];
__device__ float g_ysd[MROWS * CMODEL];
__device__ float g_states[BB * NC * NH * HD * DSTATE];
__device__ float g_prev[BB * NC * NH * HD * DSTATE];

// ---------------- mma helpers ----------------
__device__ __forceinline__ uint32_t f2tf(float f) {
    uint32_t u;
    asm("cvt.rna.tf32.f32 %0, %1;" : "=r"(u) : "f"(f));
    return u;
}
__device__ __forceinline__ void mma_tf32(float c[4], uint32_t a0, uint32_t a1, uint32_t a2, uint32_t a3,
                                         uint32_t b0, uint32_t b1) {
    asm volatile("mma.sync.aligned.m16n8k8.row.col.f32.tf32.tf32.f32 "
                 "{%0,%1,%2,%3}, {%4,%5,%6,%7}, {%8,%9}, {%0,%1,%2,%3};"
                 : "+f"(c[0]), "+f"(c[1]), "+f"(c[2]), "+f"(c[3])
                 : "r"(a0), "r"(a1), "r"(a2), "r"(a3), "r"(b0), "r"(b1));
}

// ============ kernel 1: per-pixel rmsnorm + cross-scan scatter ============
__global__ void k_rms_scan(const float* __restrict__ x, const float* __restrict__ norm_w) {
    int bx = blockIdx.x;
    int bi = bx >> 12;
    int l  = bx & 4095;
    int ch = threadIdx.x;                 // 96 threads
    float v = x[((bi * CMODEL + ch) << 12) + l];
    float ss = v * v;
    #pragma unroll
    for (int o = 16; o > 0; o >>= 1) ss += __shfl_down_sync(0xffffffffu, ss, o);
    __shared__ float sred[3];
    __shared__ float stot;
    int wid = ch >> 5, lane = ch & 31;
    if (lane == 0) sred[wid] = ss;
    __syncthreads();
    if (ch == 0) stot = sred[0] + sred[1] + sred[2];
    __syncthreads();
    float nv = v * rsqrtf(stot / 96.0f + 1.1920929e-07f) * norm_w[ch];
    int hh = l >> 6, ww = l & 63;
    int lt = (ww << 6) + hh;
    g_xs[((((bi * 4 + 0) << 12) + l) * CMODEL) + ch] = nv;
    g_xs[((((bi * 4 + 1) << 12) + (4095 - l)) * CMODEL) + ch] = nv;
    g_xs[((((bi * 4 + 2) << 12) + lt) * CMODEL) + ch] = nv;
    g_xs[((((bi * 4 + 3) << 12) + (4095 - lt)) * CMODEL) + ch] = nv;
}

// ============ kernel 2: in_proj GEMM via tf32 MMA (M=32768, N=643, K=96) ============
__global__ void k_inproj_mma(const float* __restrict__ W) {
    __shared__ uint32_t As[128][36];
    __shared__ uint32_t Bs[128][36];
    int bm = blockIdx.y * 128;
    int bn = blockIdx.x * 128;
    int tid = threadIdx.x;
    int lane = tid & 31, wid = tid >> 5;
    int wm = (wid & 1) * 64;
    int wn = (wid >> 1) * 32;
    float acc[4][4][4] = {};
    for (int kk = 0; kk < 96; kk += 32) {
        for (int i = tid; i < 128 * 8; i += 256) {
            int r = i >> 3, c = (i & 7) * 4;
            float4 v = *(const float4*)&g_xs[(bm + r) * CMODEL + kk + c];
            As[r][c + 0] = f2tf(v.x); As[r][c + 1] = f2tf(v.y);
            As[r][c + 2] = f2tf(v.z); As[r][c + 3] = f2tf(v.w);
        }
        for (int i = tid; i < 128 * 8; i += 256) {
            int r = i >> 3, c = (i & 7) * 4;
            int n = bn + r;
            float4 v = make_float4(0.f, 0.f, 0.f, 0.f);
            if (n < NPROJ) v = *(const float4*)&W[n * CMODEL + kk + c];
            Bs[r][c + 0] = f2tf(v.x); Bs[r][c + 1] = f2tf(v.y);
            Bs[r][c + 2] = f2tf(v.z); Bs[r][c + 3] = f2tf(v.w);
        }
        __syncthreads();
        #pragma unroll
        for (int k8 = 0; k8 < 32; k8 += 8) {
            uint32_t af[4][4], bf[4][2];
            int rA = lane >> 2, kA = k8 + (lane & 3);
            #pragma unroll
            for (int mi = 0; mi < 4; mi++) {
                int r = wm + mi * 16 + rA;
                af[mi][0] = As[r][kA];     af[mi][1] = As[r + 8][kA];
                af[mi][2] = As[r][kA + 4]; af[mi][3] = As[r + 8][kA + 4];
            }
            #pragma unroll
            for (int ni = 0; ni < 4; ni++) {
                int cn = wn + ni * 8 + (lane >> 2);
                bf[ni][0] = Bs[cn][kA];
                bf[ni][1] = Bs[cn][kA + 4];
            }
            #pragma unroll
            for (int mi = 0; mi < 4; mi++)
                #pragma unroll
                for (int ni = 0; ni < 4; ni++)
                    mma_tf32(acc[mi][ni], af[mi][0], af[mi][1], af[mi][2], af[mi][3],
                             bf[ni][0], bf[ni][1]);
        }
        __syncthreads();
    }
    int gid = lane >> 2, tig = lane & 3;
    #pragma unroll
    for (int mi = 0; mi < 4; mi++) {
        int r0 = bm + wm + mi * 16 + gid;
        #pragma unroll
        for (int ni = 0; ni < 4; ni++) {
            int c0 = bn + wn + ni * 8 + tig * 2;
            if (c0 < NPROJ) {
                g_zxbcdt[r0 * NPROJ + c0]       = acc[mi][ni][0];
                g_zxbcdt[(r0 + 8) * NPROJ + c0] = acc[mi][ni][2];
            }
            if (c0 + 1 < NPROJ) {
                g_zxbcdt[r0 * NPROJ + c0 + 1]       = acc[mi][ni][1];
                g_zxbcdt[(r0 + 8) * NPROJ + c0 + 1] = acc[mi][ni][3];
            }
        }
    }
}

// ============ kernel 3: dt = softplus(raw + bias);  dAc = per-chunk cumsum(dt*A) ============
__global__ void k_dt(const float* __restrict__ dt_bias, const float* __restrict__ A_log) {
    int cb = blockIdx.x;
    int t  = threadIdx.x;
    int m  = cb * CHUNK + t;
    __shared__ float sc[256];
    for (int h = 0; h < NH; h++) {
        float raw = g_zxbcdt[m * NPROJ + (DIN + CONVD) + h] + dt_bias[h];
        float dtv = (raw > 20.0f) ? raw : log1pf(expf(raw));
        g_dt[m * NH + h] = dtv;
        float Ah = -expf(A_log[h]);
        sc[t] = dtv * Ah;
        __syncthreads();
        for (int off = 1; off < 256; off <<= 1) {
            float tmp = (t >= off) ? sc[t - off] : 0.0f;
            __syncthreads();
            sc[t] += tmp;
            __syncthreads();
        }
        g_dAc[m * NH + h] = sc[t];
        __syncthreads();
    }
}

// ============ kernel 4: depthwise causal conv (k=4) + SiLU ============
__global__ void k_conv(const float* __restrict__ cw, const float* __restrict__ cb) {
    int m = blockIdx.x;
    int t = m & 4095;
    int ch = threadIdx.x;
    float acc = cb[ch];
    #pragma unroll
    for (int i = 0; i < 4; i++) {
        int tt = t - 3 + i;
        if (tt >= 0) acc = fmaf(cw[ch * 4 + i], g_zxbcdt[(m - 3 + i) * NPROJ + DIN + ch], acc);
    }
    g_xBC[m * CONVD + ch] = acc / (1.0f + expf(-acc));
}

// ============ kernel 5: intra-chunk SSD via tf32 MMA ============
// block: (bb, chunk, head, s_tile); 128 threads = 4 warps; dynamic smem
__global__ void k_intra_mma() {
    extern __shared__ uint32_t smb[];
    uint32_t (*Cs)[132]  = (uint32_t(*)[132])smb;                       // 64x132
    uint32_t (*Bs)[132]  = (uint32_t(*)[132])(smb + 64 * 132);          // 64x132
    uint32_t (*Xs)[68]   = (uint32_t(*)[68]) (smb + 2 * 64 * 132);      // 64x68
    uint32_t (*Ssm)[68]  = (uint32_t(*)[68]) (smb + 2 * 64 * 132 + 64 * 68);
    float* dAs = (float*)(smb + 2 * 64 * 132 + 2 * 64 * 68);
    float* dAt = dAs + 64;
    float* dtt = dAt + 64;

    int bx = blockIdx.x;
    int st = bx & 3;
    int rest = bx >> 2;
    int h = rest % 3; rest /= 3;
    int c = rest & 15;
    int bb = rest >> 4;
    int m0 = bb * LSEQ + c * CHUNK;
    int tid = threadIdx.x, lane = tid & 31, wid = tid >> 5;

    int sbase = m0 + st * 64;
    // load C tile (s rows x 128 states), dAs  -- once
    for (int i = tid; i < 64 * 32; i += 128) {
        int r = i >> 5, c4 = (i & 31) * 4;
        float4 v = *(const float4*)&g_xBC[(sbase + r) * CONVD + (DIN + DSTATE) + c4];
        Cs[r][c4 + 0] = f2tf(v.x); Cs[r][c4 + 1] = f2tf(v.y);
        Cs[r][c4 + 2] = f2tf(v.z); Cs[r][c4 + 3] = f2tf(v.w);
    }
    if (tid < 64) dAs[tid] = g_dAc[(sbase + tid) * NH + h];

    float accY[8][4] = {};

    for (int tt = 0; tt <= st; tt++) {
        int tbase = m0 + tt * 64;
        __syncthreads();    // prior reads of Bs/Xs/Ssm done; also publishes Cs on first iter
        for (int i = tid; i < 64 * 32; i += 128) {
            int r = i >> 5, c4 = (i & 31) * 4;
            float4 v = *(const float4*)&g_xBC[(tbase + r) * CONVD + DIN + c4];
            Bs[r][c4 + 0] = f2tf(v.x); Bs[r][c4 + 1] = f2tf(v.y);
            Bs[r][c4 + 2] = f2tf(v.z); Bs[r][c4 + 3] = f2tf(v.w);
        }
        for (int i = tid; i < 64 * 16; i += 128) {
            int r = i >> 4, c4 = (i & 15) * 4;
            float4 v = *(const float4*)&g_xBC[(tbase + r) * CONVD + h * HD + c4];
            Xs[r][c4 + 0] = f2tf(v.x); Xs[r][c4 + 1] = f2tf(v.y);
            Xs[r][c4 + 2] = f2tf(v.z); Xs[r][c4 + 3] = f2tf(v.w);
        }
        if (tid < 64) {
            dAt[tid] = g_dAc[(tbase + tid) * NH + h];
            dtt[tid] = g_dt[(tbase + tid) * NH + h];
        }
        __syncthreads();

        // GEMM1: S[s][t] = sum_n C[s][n] * B[t][n]   (warp wid: s rows wid*16..+16)
        float S[8][4] = {};
        #pragma unroll
        for (int k8 = 0; k8 < 128; k8 += 8) {
            int rA = wid * 16 + (lane >> 2), kA = k8 + (lane & 3);
            uint32_t a0 = Cs[rA][kA], a1 = Cs[rA + 8][kA];
            uint32_t a2 = Cs[rA][kA + 4], a3 = Cs[rA + 8][kA + 4];
            #pragma unroll
            for (int nf = 0; nf < 8; nf++) {
                int t = nf * 8 + (lane >> 2);
                mma_tf32(S[nf], a0, a1, a2, a3, Bs[t][kA], Bs[t][kA + 4]);
            }
        }
        // scale by exp(dA[s]-dA[t])*dt[t], causal mask on diagonal tile
        {
            int gid = lane >> 2, tig = lane & 3;
            #pragma unroll
            for (int nf = 0; nf < 8; nf++) {
                #pragma unroll
                for (int e = 0; e < 4; e++) {
                    int sl = wid * 16 + gid + ((e >= 2) ? 8 : 0);
                    int tl = nf * 8 + tig * 2 + (e & 1);
                    bool ok = (tt < st) || (tl <= sl);
                    float f = ok ? __expf(dAs[sl] - dAt[tl]) * dtt[tl] : 0.0f;
                    Ssm[sl][tl] = f2tf(S[nf][e] * f);
                }
            }
        }
        __syncthreads();
        // GEMM2: Y[s][p] += sum_t Ssm[s][t] * X[t][p]
        #pragma unroll
        for (int k8 = 0; k8 < 64; k8 += 8) {
            int rA = wid * 16 + (lane >> 2), kA = k8 + (lane & 3);
            uint32_t a0 = Ssm[rA][kA], a1 = Ssm[rA + 8][kA];
            uint32_t a2 = Ssm[rA][kA + 4], a3 = Ssm[rA + 8][kA + 4];
            #pragma unroll
            for (int nf = 0; nf < 8; nf++) {
                int p = nf * 8 + (lane >> 2);
                mma_tf32(accY[nf], a0, a1, a2, a3, Xs[kA][p], Xs[kA + 4][p]);
            }
        }
    }
    // write Y
    int gid = lane >> 2, tig = lane & 3;
    #pragma unroll
    for (int nf = 0; nf < 8; nf++) {
        int s = st * 64 + wid * 16 + gid;
        int p = nf * 8 + tig * 2;
        g_y[(m0 + s) * DIN + h * HD + p]           = accY[nf][0];
        g_y[(m0 + s) * DIN + h * HD + p + 1]       = accY[nf][1];
        g_y[(m0 + s + 8) * DIN + h * HD + p]       = accY[nf][2];
        g_y[(m0 + s + 8) * DIN + h * HD + p + 1]   = accY[nf][3];
    }
}
#define SMEM_INTRA ((2 * 64 * 132 + 2 * 64 * 68 + 3 * 64) * 4)

// ============ kernel 6: per-chunk end states ============
__global__ void k_states() {
    int bx = blockIdx.x;
    int h = bx % 3; int rest = bx / 3;
    int c = rest & 15; int bb = rest >> 4;
    int m0 = bb * LSEQ + c * CHUNK;
    __shared__ float Xh[32][65], Bw[32][129], wts[32];
    int tx = threadIdx.x, ty = threadIdx.y, tid = ty * 16 + tx;
    float dAl = g_dAc[(m0 + 255) * NH + h];
    float acc[4][8] = {};
    for (int tc = 0; tc < CHUNK; tc += 32) {
        if (tid < 32) {
            int t = tc + tid;
            wts[tid] = expf(dAl - g_dAc[(m0 + t) * NH + h]) * g_dt[(m0 + t) * NH + h];
        }
        __syncthreads();
        for (int i = tid; i < 32 * 64; i += 256) {
            int r = i >> 6, p = i & 63;
            Xh[r][p] = g_xBC[(m0 + tc + r) * CONVD + h * HD + p];
        }
        for (int i = tid; i < 32 * 128; i += 256) {
            int r = i >> 7, n = i & 127;
            Bw[r][n] = wts[r] * g_xBC[(m0 + tc + r) * CONVD + DIN + n];
        }
        __syncthreads();
        #pragma unroll
        for (int t = 0; t < 32; t++) {
            float a[4], b[8];
            #pragma unroll
            for (int i = 0; i < 4; i++) a[i] = Xh[t][ty + 16 * i];
            #pragma unroll
            for (int j = 0; j < 8; j++) b[j] = Bw[t][tx + 16 * j];
            #pragma unroll
            for (int i = 0; i < 4; i++)
                #pragma unroll
                for (int j = 0; j < 8; j++) acc[i][j] = fmaf(a[i], b[j], acc[i][j]);
        }
        __syncthreads();
    }
    int blk = (bb * 16 + c) * 3 + h;
    #pragma unroll
    for (int i = 0; i < 4; i++) {
        int p = ty + 16 * i;
        #pragma unroll
        for (int j = 0; j < 8; j++) {
            int n = tx + 16 * j;
            g_states[blk * (HD * DSTATE) + p * DSTATE + n] = acc[i][j];
        }
    }
}

// ============ kernel 7: inter-chunk recurrence ============
__global__ void k_recur() {
    int bb = blockIdx.x / 3, h = blockIdx.x % 3;
    int tid = threadIdx.x;
    float hr[32];
    #pragma unroll
    for (int r = 0; r < 32; r++) hr[r] = 0.0f;
    for (int c = 0; c < NC; c++) {
        int blk = (bb * 16 + c) * 3 + h;
        float decay = expf(g_dAc[(bb * LSEQ + c * CHUNK + 255) * NH + h]);
        #pragma unroll
        for (int r = 0; r < 32; r++) {
            int idx = blk * (HD * DSTATE) + r * 256 + tid;
            g_prev[idx] = hr[r];
            hr[r] = fmaf(decay, hr[r], g_states[idx]);
        }
    }
}

// ============ kernel 8: inter-chunk y correction + D*x ============
__global__ void k_ycorr(const float* __restrict__ Dp) {
    int bx = blockIdx.x;
    int h = bx % 3; int rest = bx / 3;
    int c = rest & 15; int bb = rest >> 4;
    int m0 = bb * LSEQ + c * CHUNK;
    int blk = (bb * 16 + c) * 3 + h;
    __shared__ float prevS[64][129];
    __shared__ float Cs2[64][33];
    int tx = threadIdx.x, ty = threadIdx.y, tid = ty * 16 + tx;
    for (int i = tid; i < HD * DSTATE; i += 256) {
        int p = i >> 7, n = i & 127;
        prevS[p][n] = g_prev[blk * (HD * DSTATE) + i];
    }
    float Dh = Dp[h];
    for (int stile = 0; stile < 4; stile++) {
        float acc[4][4] = {};
        for (int kk = 0; kk < 128; kk += 32) {
            for (int i = tid; i < 64 * 32; i += 256) {
                int r = i >> 5, k = i & 31;
                Cs2[r][k] = g_xBC[(m0 + stile * 64 + r) * CONVD + (DIN + DSTATE) + kk + k];
            }
            __syncthreads();
            #pragma unroll
            for (int k = 0; k < 32; k++) {
                float a[4], b[4];
                #pragma unroll
                for (int i = 0; i < 4; i++) a[i] = Cs2[ty + 16 * i][k];
                #pragma unroll
                for (int j = 0; j < 4; j++) b[j] = prevS[tx + 16 * j][kk + k];
                #pragma unroll
                for (int i = 0; i < 4; i++)
                    #pragma unroll
                    for (int j = 0; j < 4; j++) acc[i][j] = fmaf(a[i], b[j], acc[i][j]);
            }
            __syncthreads();
        }
        #pragma unroll
        for (int i = 0; i < 4; i++) {
            int s = stile * 64 + ty + 16 * i;
            int m = m0 + s;
            float eA = expf(g_dAc[m * NH + h]);
            #pragma unroll
            for (int j = 0; j < 4; j++) {
                int p = tx + 16 * j;
                float xv = g_xBC[m * CONVD + h * HD + p];
                g_y[m * DIN + h * HD + p] += eA * acc[i][j] + Dh * xv;
            }
        }
    }
}

// ============ kernel 9: gating + rmsnorm ============
__global__ void k_gate(const float* __restrict__ gw) {
    int m = blockIdx.x;
    int d = threadIdx.x;
    float y = g_y[m * DIN + d];
    float z = g_zxbcdt[m * NPROJ + d];
    float v = y * (z / (1.0f + expf(-z)));
    float ss = v * v;
    #pragma unroll
    for (int o = 16; o > 0; o >>= 1) ss += __shfl_down_sync(0xffffffffu, ss, o);
    __shared__ float sred[6];
    __shared__ float stot;
    int wid = d >> 5, lane = d & 31;
    if (lane == 0) sred[wid] = ss;
    __syncthreads();
    if (d == 0) stot = sred[0] + sred[1] + sred[2] + sred[3] + sred[4] + sred[5];
    __syncthreads();
    g_yn[m * DIN + d] = v * rsqrtf(stot / 192.0f + 1e-5f) * gw[d];
}

// ============ kernel 10: out_proj GEMM (M=32768, N=96, K=192) ============
__global__ void k_outproj(const float* __restrict__ W) {
    __shared__ float As[64][33];
    __shared__ float Bs[96][33];
    int bm = blockIdx.x * 64;
    int tx = threadIdx.x, ty = threadIdx.y, tid = ty * 16 + tx;
    float acc[4][6] = {};
    for (int kk = 0; kk < 192; kk += 32) {
        for (int i = tid; i < 64 * 32; i += 256) {
            int r = i >> 5, k = i & 31;
            As[r][k] = g_yn[(bm + r) * DIN + kk + k];
        }
        for (int i = tid; i < 96 * 32; i += 256) {
            int r = i >> 5, k = i & 31;
            Bs[r][k] = W[r * DIN + kk + k];
        }
        __syncthreads();
        #pragma unroll
        for (int k = 0; k < 32; k++) {
            float a[4], b[6];
            #pragma unroll
            for (int i = 0; i < 4; i++) a[i] = As[ty + 16 * i][k];
            #pragma unroll
            for (int j = 0; j < 6; j++) b[j] = Bs[tx + 16 * j][k];
            #pragma unroll
            for (int i = 0; i < 4; i++)
                #pragma unroll
                for (int j = 0; j < 6; j++) acc[i][j] = fmaf(a[i], b[j], acc[i][j]);
        }
        __syncthreads();
    }
    #pragma unroll
    for (int i = 0; i < 4; i++) {
        int row = bm + ty + 16 * i;
        #pragma unroll
        for (int j = 0; j < 6; j++) {
            g_ysd[row * CMODEL + tx + 16 * j] = acc[i][j];
        }
    }
}

// ============ kernel 11: un-scan + residual ============
__global__ void k_unscan(const float* __restrict__ x, float* __restrict__ out) {
    int bx = blockIdx.x;
    int bi = bx >> 12;
    int l  = bx & 4095;
    int ch = threadIdx.x;
    int hh = l >> 6, ww = l & 63;
    int lt = (ww << 6) + hh;
    float v = g_ysd[((((bi * 4 + 0) << 12) + l) * CMODEL) + ch]
            + g_ysd[((((bi * 4 + 1) << 12) + (4095 - l)) * CMODEL) + ch]
            + g_ysd[((((bi * 4 + 2) << 12) + lt) * CMODEL) + ch]
            + g_ysd[((((bi * 4 + 3) << 12) + (4095 - lt)) * CMODEL) + ch];
    int idx = ((bi * CMODEL + ch) << 12) + l;
    out[idx] = x[idx] + 0.25f * v;
}

// ---------------- launch ----------------
extern "C" void kernel_launch(void* const* d_in, const int* in_sizes, int n_in,
                              void* d_out, int out_size) {
    const float* x          = (const float*)d_in[0];
    const float* norm_w     = (const float*)d_in[1];
    const float* in_proj_w  = (const float*)d_in[2];
    const float* conv_w     = (const float*)d_in[3];
    const float* conv_b     = (const float*)d_in[4];
    const float* dt_bias    = (const float*)d_in[5];
    const float* A_log      = (const float*)d_in[6];
    const float* Dp         = (const float*)d_in[7];
    const float* gnorm_w    = (const float*)d_in[8];
    const float* out_proj_w = (const float*)d_in[9];
    float* out = (float*)d_out;

    static int smem_set = 0;
    if (!smem_set) {
        cudaFuncSetAttribute(k_intra_mma, cudaFuncAttributeMaxDynamicSharedMemorySize, SMEM_INTRA);
        smem_set = 1;
    }

    dim3 t16(16, 16);

    k_rms_scan<<<BATCH * LSEQ, CMODEL>>>(x, norm_w);
    k_inproj_mma<<<dim3(6, MROWS / 128), 256>>>(in_proj_w);
    k_dt<<<BB * NC, CHUNK>>>(dt_bias, A_log);
    k_conv<<<MROWS, CONVD>>>(conv_w, conv_b);
    k_intra_mma<<<BB * NC * NH * 4, 128, SMEM_INTRA>>>();
    k_states<<<BB * NC * NH, t16>>>();
    k_recur<<<BB * NH, 256>>>();
    k_ycorr<<<BB * NC * NH, t16>>>(Dp);
    k_gate<<<MROWS, DIN>>>(gnorm_w);
    k_outproj<<<MROWS / 64, t16>>>(out_proj_w);
    k_unscan<<<BATCH * LSEQ, CMODEL>>>(x, out);
}

// round 3
// speedup vs baseline: 1.7503x; 1.3387x over previous
#include <cuda_runtime.h>
#include <cuda_bf16.h>
#include <math.h>
#include <stdint.h>

// ---------------- problem constants ----------------
#define BATCH   2
#define CMODEL  96
#define LSEQ    4096
#define BB      8
#define DIN     192
#define DSTATE  128
#define CONVD   448
#define NH      3
#define HD      64
#define NPROJ   643
#define NPROJ_S 644             // padded stride (16B-aligned rows)
#define CHUNK   256
#define NC      16
#define MROWS   (BB*LSEQ)       // 32768

// ---------------- scratch ----------------
__device__ float g_xs[MROWS * CMODEL];
__device__ float g_zxbcdt[MROWS * NPROJ_S];
__device__ float g_xBC[MROWS * CONVD];
__device__ float g_dt[MROWS * NH];
__device__ float g_dAc[MROWS * NH];
__device__ float g_y[MROWS * DIN];
__device__ float g_yn[MROWS * DIN];
__device__ float g_ysd[MROWS * CMODEL];
__device__ float g_states[BB * NC * NH * HD * DSTATE];
__device__ float g_prev[BB * NC * NH * HD * DSTATE];

// ---------------- mma helpers ----------------
__device__ __forceinline__ uint32_t f2tf(float f) {
    uint32_t u;
    asm("cvt.rna.tf32.f32 %0, %1;" : "=r"(u) : "f"(f));
    return u;
}
__device__ __forceinline__ void mma_tf32(float c[4], uint32_t a0, uint32_t a1, uint32_t a2, uint32_t a3,
                                         uint32_t b0, uint32_t b1) {
    asm volatile("mma.sync.aligned.m16n8k8.row.col.f32.tf32.tf32.f32 "
                 "{%0,%1,%2,%3}, {%4,%5,%6,%7}, {%8,%9}, {%0,%1,%2,%3};"
                 : "+f"(c[0]), "+f"(c[1]), "+f"(c[2]), "+f"(c[3])
                 : "r"(a0), "r"(a1), "r"(a2), "r"(a3), "r"(b0), "r"(b1));
}

// ============ kernel 1: rmsnorm + cross-scan, tiled & coalesced ============
__global__ void k_rms_scan(const float* __restrict__ x, const float* __restrict__ norm_w) {
    __shared__ float sx[96][33];
    __shared__ float rs[32];
    __shared__ float wsh[96];
    int bi = blockIdx.x >> 7;
    int l0 = (blockIdx.x & 127) * 32;
    int tid = threadIdx.x;                 // 256
    if (tid < 96) wsh[tid] = norm_w[tid];
    for (int i = tid; i < 96 * 32; i += 256) {
        int ch = i >> 5, ll = i & 31;
        sx[ch][ll] = x[((bi * 96 + ch) << 12) + l0 + ll];
    }
    __syncthreads();
    if (tid < 32) {
        float ssum = 0.f;
        #pragma unroll 8
        for (int ch = 0; ch < 96; ch++) { float v = sx[ch][tid]; ssum = fmaf(v, v, ssum); }
        rs[tid] = rsqrtf(ssum / 96.0f + 1.1920929e-07f);
    }
    __syncthreads();
    for (int i = tid; i < 3072; i += 256) {
        int ll = i / 96, ch = i - ll * 96;
        int l = l0 + ll;
        float nv = sx[ch][ll] * rs[ll] * wsh[ch];
        int hh = l >> 6, ww = l & 63;
        int lt = (ww << 6) + hh;
        g_xs[(((bi * 4 + 0) << 12) + l) * 96 + ch] = nv;
        g_xs[(((bi * 4 + 1) << 12) + (4095 - l)) * 96 + ch] = nv;
        g_xs[(((bi * 4 + 2) << 12) + lt) * 96 + ch] = nv;
        g_xs[(((bi * 4 + 3) << 12) + (4095 - lt)) * 96 + ch] = nv;
    }
}

// ============ kernel 2: in_proj GEMM via tf32 MMA (M=32768, N=643, K=96) ============
__global__ void k_inproj_mma(const float* __restrict__ W) {
    __shared__ uint32_t As[128][36];
    __shared__ uint32_t Bs[128][36];
    int bm = blockIdx.y * 128;
    int bn = blockIdx.x * 128;
    int tid = threadIdx.x;
    int lane = tid & 31, wid = tid >> 5;
    int wm = (wid & 1) * 64;
    int wn = (wid >> 1) * 32;
    float acc[4][4][4] = {};
    for (int kk = 0; kk < 96; kk += 32) {
        for (int i = tid; i < 128 * 8; i += 256) {
            int r = i >> 3, c = (i & 7) * 4;
            float4 v = *(const float4*)&g_xs[(bm + r) * CMODEL + kk + c];
            As[r][c + 0] = f2tf(v.x); As[r][c + 1] = f2tf(v.y);
            As[r][c + 2] = f2tf(v.z); As[r][c + 3] = f2tf(v.w);
        }
        for (int i = tid; i < 128 * 8; i += 256) {
            int r = i >> 3, c = (i & 7) * 4;
            int n = bn + r;
            float4 v = make_float4(0.f, 0.f, 0.f, 0.f);
            if (n < NPROJ) v = *(const float4*)&W[n * CMODEL + kk + c];
            Bs[r][c + 0] = f2tf(v.x); Bs[r][c + 1] = f2tf(v.y);
            Bs[r][c + 2] = f2tf(v.z); Bs[r][c + 3] = f2tf(v.w);
        }
        __syncthreads();
        #pragma unroll
        for (int k8 = 0; k8 < 32; k8 += 8) {
            uint32_t af[4][4], bf[4][2];
            int rA = lane >> 2, kA = k8 + (lane & 3);
            #pragma unroll
            for (int mi = 0; mi < 4; mi++) {
                int r = wm + mi * 16 + rA;
                af[mi][0] = As[r][kA];     af[mi][1] = As[r + 8][kA];
                af[mi][2] = As[r][kA + 4]; af[mi][3] = As[r + 8][kA + 4];
            }
            #pragma unroll
            for (int ni = 0; ni < 4; ni++) {
                int cn = wn + ni * 8 + (lane >> 2);
                bf[ni][0] = Bs[cn][kA];
                bf[ni][1] = Bs[cn][kA + 4];
            }
            #pragma unroll
            for (int mi = 0; mi < 4; mi++)
                #pragma unroll
                for (int ni = 0; ni < 4; ni++)
                    mma_tf32(acc[mi][ni], af[mi][0], af[mi][1], af[mi][2], af[mi][3],
                             bf[ni][0], bf[ni][1]);
        }
        __syncthreads();
    }
    int gid = lane >> 2, tig = lane & 3;
    #pragma unroll
    for (int mi = 0; mi < 4; mi++) {
        int r0 = bm + wm + mi * 16 + gid;
        #pragma unroll
        for (int ni = 0; ni < 4; ni++) {
            int c0 = bn + wn + ni * 8 + tig * 2;
            if (c0 < NPROJ) {
                g_zxbcdt[r0 * NPROJ_S + c0]       = acc[mi][ni][0];
                g_zxbcdt[(r0 + 8) * NPROJ_S + c0] = acc[mi][ni][2];
            }
            if (c0 + 1 < NPROJ) {
                g_zxbcdt[r0 * NPROJ_S + c0 + 1]       = acc[mi][ni][1];
                g_zxbcdt[(r0 + 8) * NPROJ_S + c0 + 1] = acc[mi][ni][3];
            }
        }
    }
}

// ============ kernel 3: dt softplus + per-chunk cumsum via warp scan ============
__global__ void k_dt(const float* __restrict__ dt_bias, const float* __restrict__ A_log) {
    int cb = blockIdx.x;
    int t  = threadIdx.x;                 // 256
    int m  = cb * CHUNK + t;
    int lane = t & 31, wid = t >> 5;
    __shared__ float wsum[8], woff[8];
    for (int h = 0; h < NH; h++) {
        float raw = g_zxbcdt[m * NPROJ_S + (DIN + CONVD) + h] + dt_bias[h];
        float dtv = (raw > 20.0f) ? raw : log1pf(expf(raw));
        g_dt[m * NH + h] = dtv;
        float Ah = -expf(A_log[h]);
        float s = dtv * Ah;
        #pragma unroll
        for (int o = 1; o < 32; o <<= 1) {
            float n = __shfl_up_sync(0xffffffffu, s, o);
            if (lane >= o) s += n;
        }
        if (lane == 31) wsum[wid] = s;
        __syncthreads();
        if (t < 8) {
            float ws = wsum[t];
            #pragma unroll
            for (int o = 1; o < 8; o <<= 1) {
                float n = __shfl_up_sync(0xffu, ws, o);
                if (t >= o) ws += n;
            }
            woff[t] = ws;
        }
        __syncthreads();
        float off = wid ? woff[wid - 1] : 0.0f;
        g_dAc[m * NH + h] = s + off;
        __syncthreads();
    }
}

// ============ kernel 4: depthwise causal conv + SiLU, float4 ============
__global__ void k_conv(const float* __restrict__ cw, const float* __restrict__ cb) {
    int tid = threadIdx.x;                 // 448
    int mloc = tid / 112, cg = tid - mloc * 112;
    int m = blockIdx.x * 4 + mloc;
    int t = m & 4095;
    int c4 = cg * 4;
    float4 w0 = *(const float4*)&cw[(c4 + 0) * 4];
    float4 w1 = *(const float4*)&cw[(c4 + 1) * 4];
    float4 w2 = *(const float4*)&cw[(c4 + 2) * 4];
    float4 w3 = *(const float4*)&cw[(c4 + 3) * 4];
    float4 acc = *(const float4*)&cb[c4];
    #pragma unroll
    for (int i = 0; i < 4; i++) {
        int tt = t - 3 + i;
        if (tt >= 0) {
            float4 v = *(const float4*)&g_zxbcdt[(size_t)(m - 3 + i) * NPROJ_S + DIN + c4];
            acc.x = fmaf((&w0.x)[i], v.x, acc.x);
            acc.y = fmaf((&w1.x)[i], v.y, acc.y);
            acc.z = fmaf((&w2.x)[i], v.z, acc.z);
            acc.w = fmaf((&w3.x)[i], v.w, acc.w);
        }
    }
    float4 o;
    o.x = acc.x / (1.0f + expf(-acc.x));
    o.y = acc.y / (1.0f + expf(-acc.y));
    o.z = acc.z / (1.0f + expf(-acc.z));
    o.w = acc.w / (1.0f + expf(-acc.w));
    *(float4*)&g_xBC[m * CONVD + c4] = o;
}

// ============ kernel 5: intra-chunk SSD via tf32 MMA ============
__global__ void k_intra_mma() {
    extern __shared__ uint32_t smb[];
    uint32_t (*Cs)[132]  = (uint32_t(*)[132])smb;
    uint32_t (*Bs)[132]  = (uint32_t(*)[132])(smb + 64 * 132);
    uint32_t (*Xs)[68]   = (uint32_t(*)[68]) (smb + 2 * 64 * 132);
    uint32_t (*Ssm)[68]  = (uint32_t(*)[68]) (smb + 2 * 64 * 132 + 64 * 68);
    float* dAs = (float*)(smb + 2 * 64 * 132 + 2 * 64 * 68);
    float* dAt = dAs + 64;
    float* dtt = dAt + 64;

    int bx = blockIdx.x;
    int st = bx & 3;
    int rest = bx >> 2;
    int h = rest % 3; rest /= 3;
    int c = rest & 15;
    int bb = rest >> 4;
    int m0 = bb * LSEQ + c * CHUNK;
    int tid = threadIdx.x, lane = tid & 31, wid = tid >> 5;

    int sbase = m0 + st * 64;
    for (int i = tid; i < 64 * 32; i += 128) {
        int r = i >> 5, c4 = (i & 31) * 4;
        float4 v = *(const float4*)&g_xBC[(sbase + r) * CONVD + (DIN + DSTATE) + c4];
        Cs[r][c4 + 0] = f2tf(v.x); Cs[r][c4 + 1] = f2tf(v.y);
        Cs[r][c4 + 2] = f2tf(v.z); Cs[r][c4 + 3] = f2tf(v.w);
    }
    if (tid < 64) dAs[tid] = g_dAc[(sbase + tid) * NH + h];

    float accY[8][4] = {};

    for (int tt = 0; tt <= st; tt++) {
        int tbase = m0 + tt * 64;
        __syncthreads();
        for (int i = tid; i < 64 * 32; i += 128) {
            int r = i >> 5, c4 = (i & 31) * 4;
            float4 v = *(const float4*)&g_xBC[(tbase + r) * CONVD + DIN + c4];
            Bs[r][c4 + 0] = f2tf(v.x); Bs[r][c4 + 1] = f2tf(v.y);
            Bs[r][c4 + 2] = f2tf(v.z); Bs[r][c4 + 3] = f2tf(v.w);
        }
        for (int i = tid; i < 64 * 16; i += 128) {
            int r = i >> 4, c4 = (i & 15) * 4;
            float4 v = *(const float4*)&g_xBC[(tbase + r) * CONVD + h * HD + c4];
            Xs[r][c4 + 0] = f2tf(v.x); Xs[r][c4 + 1] = f2tf(v.y);
            Xs[r][c4 + 2] = f2tf(v.z); Xs[r][c4 + 3] = f2tf(v.w);
        }
        if (tid < 64) {
            dAt[tid] = g_dAc[(tbase + tid) * NH + h];
            dtt[tid] = g_dt[(tbase + tid) * NH + h];
        }
        __syncthreads();

        float S[8][4] = {};
        #pragma unroll
        for (int k8 = 0; k8 < 128; k8 += 8) {
            int rA = wid * 16 + (lane >> 2), kA = k8 + (lane & 3);
            uint32_t a0 = Cs[rA][kA], a1 = Cs[rA + 8][kA];
            uint32_t a2 = Cs[rA][kA + 4], a3 = Cs[rA + 8][kA + 4];
            #pragma unroll
            for (int nf = 0; nf < 8; nf++) {
                int t = nf * 8 + (lane >> 2);
                mma_tf32(S[nf], a0, a1, a2, a3, Bs[t][kA], Bs[t][kA + 4]);
            }
        }
        {
            int gid = lane >> 2, tig = lane & 3;
            #pragma unroll
            for (int nf = 0; nf < 8; nf++) {
                #pragma unroll
                for (int e = 0; e < 4; e++) {
                    int sl = wid * 16 + gid + ((e >= 2) ? 8 : 0);
                    int tl = nf * 8 + tig * 2 + (e & 1);
                    bool ok = (tt < st) || (tl <= sl);
                    float f = ok ? __expf(dAs[sl] - dAt[tl]) * dtt[tl] : 0.0f;
                    Ssm[sl][tl] = f2tf(S[nf][e] * f);
                }
            }
        }
        __syncthreads();
        #pragma unroll
        for (int k8 = 0; k8 < 64; k8 += 8) {
            int rA = wid * 16 + (lane >> 2), kA = k8 + (lane & 3);
            uint32_t a0 = Ssm[rA][kA], a1 = Ssm[rA + 8][kA];
            uint32_t a2 = Ssm[rA][kA + 4], a3 = Ssm[rA + 8][kA + 4];
            #pragma unroll
            for (int nf = 0; nf < 8; nf++) {
                int p = nf * 8 + (lane >> 2);
                mma_tf32(accY[nf], a0, a1, a2, a3, Xs[kA][p], Xs[kA + 4][p]);
            }
        }
    }
    int gid = lane >> 2, tig = lane & 3;
    #pragma unroll
    for (int nf = 0; nf < 8; nf++) {
        int s = st * 64 + wid * 16 + gid;
        int p = nf * 8 + tig * 2;
        g_y[(m0 + s) * DIN + h * HD + p]           = accY[nf][0];
        g_y[(m0 + s) * DIN + h * HD + p + 1]       = accY[nf][1];
        g_y[(m0 + s + 8) * DIN + h * HD + p]       = accY[nf][2];
        g_y[(m0 + s + 8) * DIN + h * HD + p + 1]   = accY[nf][3];
    }
}
#define SMEM_INTRA ((2 * 64 * 132 + 2 * 64 * 68 + 3 * 64) * 4)

// ============ kernel 6: per-chunk end states via tf32 MMA ============
// states[p][n] = sum_t (wt[t]*x[t][p]) ... A[p][t]=x[t][p], B[t][n]=wt[t]*Bx[t][n]
__global__ void k_states() {
    __shared__ uint32_t Xs[32][72];
    __shared__ uint32_t Bw[32][136];
    __shared__ float wts[32];
    int bx = blockIdx.x;
    int h = bx % 3; int rest = bx / 3;
    int c = rest & 15; int bb = rest >> 4;
    int m0 = bb * LSEQ + c * CHUNK;
    int tid = threadIdx.x, lane = tid & 31, wid = tid >> 5;   // 256 thr / 8 warps
    int wm = (wid & 3) * 16;
    int wn = (wid >> 2) * 64;
    float dAl = g_dAc[(m0 + 255) * NH + h];
    float acc[8][4] = {};
    for (int tc = 0; tc < CHUNK; tc += 32) {
        __syncthreads();
        if (tid < 32) {
            int t = tc + tid;
            wts[tid] = expf(dAl - g_dAc[(m0 + t) * NH + h]) * g_dt[(m0 + t) * NH + h];
        }
        __syncthreads();
        for (int i = tid; i < 32 * 16; i += 256) {
            int r = i >> 4, c4 = (i & 15) * 4;
            float4 v = *(const float4*)&g_xBC[(m0 + tc + r) * CONVD + h * HD + c4];
            Xs[r][c4 + 0] = f2tf(v.x); Xs[r][c4 + 1] = f2tf(v.y);
            Xs[r][c4 + 2] = f2tf(v.z); Xs[r][c4 + 3] = f2tf(v.w);
        }
        for (int i = tid; i < 32 * 32; i += 256) {
            int r = i >> 5, c4 = (i & 31) * 4;
            float w = wts[r];
            float4 v = *(const float4*)&g_xBC[(m0 + tc + r) * CONVD + DIN + c4];
            Bw[r][c4 + 0] = f2tf(w * v.x); Bw[r][c4 + 1] = f2tf(w * v.y);
            Bw[r][c4 + 2] = f2tf(w * v.z); Bw[r][c4 + 3] = f2tf(w * v.w);
        }
        __syncthreads();
        #pragma unroll
        for (int k8 = 0; k8 < 32; k8 += 8) {
            int rA = wm + (lane >> 2), kA = k8 + (lane & 3);
            uint32_t a0 = Xs[kA][rA],     a1 = Xs[kA][rA + 8];
            uint32_t a2 = Xs[kA + 4][rA], a3 = Xs[kA + 4][rA + 8];
            #pragma unroll
            for (int ni = 0; ni < 8; ni++) {
                int cn = wn + ni * 8 + (lane >> 2);
                mma_tf32(acc[ni], a0, a1, a2, a3, Bw[kA][cn], Bw[kA + 4][cn]);
            }
        }
    }
    int blk = (bb * 16 + c) * 3 + h;
    int gid = lane >> 2, tig = lane & 3;
    #pragma unroll
    for (int ni = 0; ni < 8; ni++) {
        int p0 = wm + gid;
        int n0 = wn + ni * 8 + tig * 2;
        float* dst = &g_states[blk * (HD * DSTATE)];
        dst[p0 * DSTATE + n0]           = acc[ni][0];
        dst[p0 * DSTATE + n0 + 1]       = acc[ni][1];
        dst[(p0 + 8) * DSTATE + n0]     = acc[ni][2];
        dst[(p0 + 8) * DSTATE + n0 + 1] = acc[ni][3];
    }
}

// ============ kernel 7: inter-chunk recurrence (192 blocks) ============
__global__ void k_recur() {
    int bxs = blockIdx.x;          // 192
    int slice = bxs & 7;
    int bh = bxs >> 3;
    int bb = bh / 3, h = bh % 3;
    int tid = threadIdx.x;         // 256
    float hr[4] = {0.f, 0.f, 0.f, 0.f};
    for (int c = 0; c < NC; c++) {
        int blk = (bb * 16 + c) * 3 + h;
        float decay = expf(g_dAc[(bb * LSEQ + c * CHUNK + 255) * NH + h]);
        #pragma unroll
        for (int r = 0; r < 4; r++) {
            int idx = blk * (HD * DSTATE) + slice * 1024 + r * 256 + tid;
            g_prev[idx] = hr[r];
            hr[r] = fmaf(decay, hr[r], g_states[idx]);
        }
    }
}

// ============ kernel 8: inter-chunk y correction via tf32 MMA + D*x ============
__global__ void k_ycorr(const float* __restrict__ Dp) {
    extern __shared__ uint32_t ysm[];
    uint32_t (*prevS)[132] = (uint32_t(*)[132])ysm;
    uint32_t (*Cs)[132]    = (uint32_t(*)[132])(ysm + 64 * 132);
    float* exps            = (float*)(ysm + 2 * 64 * 132);
    int bx = blockIdx.x;
    int h = bx % 3; int rest = bx / 3;
    int c = rest & 15; int bb = rest >> 4;
    int m0 = bb * LSEQ + c * CHUNK;
    int blk = (bb * 16 + c) * 3 + h;
    int tid = threadIdx.x, lane = tid & 31, wid = tid >> 5;   // 128 thr / 4 warps
    float Dh = Dp[h];
    for (int i = tid; i < 64 * 32; i += 128) {
        int p = i >> 5, c4 = (i & 31) * 4;
        float4 v = *(const float4*)&g_prev[blk * (HD * DSTATE) + p * DSTATE + c4];
        prevS[p][c4 + 0] = f2tf(v.x); prevS[p][c4 + 1] = f2tf(v.y);
        prevS[p][c4 + 2] = f2tf(v.z); prevS[p][c4 + 3] = f2tf(v.w);
    }
    int gid = lane >> 2, tig = lane & 3;
    for (int stile = 0; stile < 4; stile++) {
        __syncthreads();
        for (int i = tid; i < 64 * 32; i += 128) {
            int r = i >> 5, c4 = (i & 31) * 4;
            float4 v = *(const float4*)&g_xBC[(m0 + stile * 64 + r) * CONVD + (DIN + DSTATE) + c4];
            Cs[r][c4 + 0] = f2tf(v.x); Cs[r][c4 + 1] = f2tf(v.y);
            Cs[r][c4 + 2] = f2tf(v.z); Cs[r][c4 + 3] = f2tf(v.w);
        }
        if (tid < 64) exps[tid] = expf(g_dAc[(m0 + stile * 64 + tid) * NH + h]);
        __syncthreads();
        float acc[8][4] = {};
        #pragma unroll
        for (int k8 = 0; k8 < 128; k8 += 8) {
            int rA = wid * 16 + gid, kA = k8 + (lane & 3);
            uint32_t a0 = Cs[rA][kA],     a1 = Cs[rA + 8][kA];
            uint32_t a2 = Cs[rA][kA + 4], a3 = Cs[rA + 8][kA + 4];
            #pragma unroll
            for (int ni = 0; ni < 8; ni++) {
                int cn = ni * 8 + gid;
                mma_tf32(acc[ni], a0, a1, a2, a3, prevS[cn][kA], prevS[cn][kA + 4]);
            }
        }
        #pragma unroll
        for (int ni = 0; ni < 8; ni++) {
            int p = ni * 8 + tig * 2;
            int s0 = wid * 16 + gid;
            int m1 = m0 + stile * 64 + s0;
            int m2 = m1 + 8;
            float eA1 = exps[s0], eA2 = exps[s0 + 8];
            float xv10 = g_xBC[m1 * CONVD + h * HD + p];
            float xv11 = g_xBC[m1 * CONVD + h * HD + p + 1];
            float xv20 = g_xBC[m2 * CONVD + h * HD + p];
            float xv21 = g_xBC[m2 * CONVD + h * HD + p + 1];
            g_y[m1 * DIN + h * HD + p]     += eA1 * acc[ni][0] + Dh * xv10;
            g_y[m1 * DIN + h * HD + p + 1] += eA1 * acc[ni][1] + Dh * xv11;
            g_y[m2 * DIN + h * HD + p]     += eA2 * acc[ni][2] + Dh * xv20;
            g_y[m2 * DIN + h * HD + p + 1] += eA2 * acc[ni][3] + Dh * xv21;
        }
    }
}
#define SMEM_YCORR ((2 * 64 * 132) * 4 + 64 * 4)

// ============ kernel 9: gating + rmsnorm ============
__global__ void k_gate(const float* __restrict__ gw) {
    int m = blockIdx.x;
    int d = threadIdx.x;
    float y = g_y[m * DIN + d];
    float z = g_zxbcdt[m * NPROJ_S + d];
    float v = y * (z / (1.0f + expf(-z)));
    float ss = v * v;
    #pragma unroll
    for (int o = 16; o > 0; o >>= 1) ss += __shfl_down_sync(0xffffffffu, ss, o);
    __shared__ float sred[6];
    __shared__ float stot;
    int wid = d >> 5, lane = d & 31;
    if (lane == 0) sred[wid] = ss;
    __syncthreads();
    if (d == 0) stot = sred[0] + sred[1] + sred[2] + sred[3] + sred[4] + sred[5];
    __syncthreads();
    g_yn[m * DIN + d] = v * rsqrtf(stot / 192.0f + 1e-5f) * gw[d];
}

// ============ kernel 10: out_proj GEMM via tf32 MMA (M=32768, N=96, K=192) ============
__global__ void k_outproj(const float* __restrict__ W) {
    __shared__ uint32_t As[128][36];
    __shared__ uint32_t Bs[96][36];
    int bm = blockIdx.x * 128;
    int tid = threadIdx.x, lane = tid & 31, wid = tid >> 5;   // 256 thr / 8 warps
    int wm = (wid & 3) * 32;
    int wn = (wid >> 2) * 48;
    float acc[2][6][4] = {};
    for (int kk = 0; kk < 192; kk += 32) {
        for (int i = tid; i < 128 * 8; i += 256) {
            int r = i >> 3, c4 = (i & 7) * 4;
            float4 v = *(const float4*)&g_yn[(bm + r) * DIN + kk + c4];
            As[r][c4 + 0] = f2tf(v.x); As[r][c4 + 1] = f2tf(v.y);
            As[r][c4 + 2] = f2tf(v.z); As[r][c4 + 3] = f2tf(v.w);
        }
        for (int i = tid; i < 96 * 8; i += 256) {
            int r = i >> 3, c4 = (i & 7) * 4;
            float4 v = *(const float4*)&W[r * DIN + kk + c4];
            Bs[r][c4 + 0] = f2tf(v.x); Bs[r][c4 + 1] = f2tf(v.y);
            Bs[r][c4 + 2] = f2tf(v.z); Bs[r][c4 + 3] = f2tf(v.w);
        }
        __syncthreads();
        #pragma unroll
        for (int k8 = 0; k8 < 32; k8 += 8) {
            int kA = k8 + (lane & 3);
            uint32_t af[2][4];
            #pragma unroll
            for (int mi = 0; mi < 2; mi++) {
                int r = wm + mi * 16 + (lane >> 2);
                af[mi][0] = As[r][kA];     af[mi][1] = As[r + 8][kA];
                af[mi][2] = As[r][kA + 4]; af[mi][3] = As[r + 8][kA + 4];
            }
            #pragma unroll
            for (int ni = 0; ni < 6; ni++) {
                int cn = wn + ni * 8 + (lane >> 2);
                uint32_t b0 = Bs[cn][kA], b1 = Bs[cn][kA + 4];
                #pragma unroll
                for (int mi = 0; mi < 2; mi++)
                    mma_tf32(acc[mi][ni], af[mi][0], af[mi][1], af[mi][2], af[mi][3], b0, b1);
            }
        }
        __syncthreads();
    }
    int gid = lane >> 2, tig = lane & 3;
    #pragma unroll
    for (int mi = 0; mi < 2; mi++) {
        int r0 = bm + wm + mi * 16 + gid;
        #pragma unroll
        for (int ni = 0; ni < 6; ni++) {
            int c0 = wn + ni * 8 + tig * 2;
            g_ysd[r0 * CMODEL + c0]           = acc[mi][ni][0];
            g_ysd[r0 * CMODEL + c0 + 1]       = acc[mi][ni][1];
            g_ysd[(r0 + 8) * CMODEL + c0]     = acc[mi][ni][2];
            g_ysd[(r0 + 8) * CMODEL + c0 + 1] = acc[mi][ni][3];
        }
    }
}

// ============ kernel 11: un-scan + residual, tiled & coalesced ============
__global__ void k_unscan(const float* __restrict__ x, float* __restrict__ out) {
    __shared__ float sy[96][33];
    int bi = blockIdx.x >> 7;
    int l0 = (blockIdx.x & 127) * 32;
    int tid = threadIdx.x;                 // 256
    for (int i = tid; i < 3072; i += 256) {
        int ll = i / 96, ch = i - ll * 96;
        int l = l0 + ll;
        int hh = l >> 6, ww = l & 63;
        int lt = (ww << 6) + hh;
        float v = g_ysd[(((bi * 4 + 0) << 12) + l) * 96 + ch]
                + g_ysd[(((bi * 4 + 1) << 12) + (4095 - l)) * 96 + ch]
                + g_ysd[(((bi * 4 + 2) << 12) + lt) * 96 + ch]
                + g_ysd[(((bi * 4 + 3) << 12) + (4095 - lt)) * 96 + ch];
        sy[ch][ll] = 0.25f * v;
    }
    __syncthreads();
    for (int i = tid; i < 96 * 32; i += 256) {
        int ch = i >> 5, ll = i & 31;
        int idx = ((bi * 96 + ch) << 12) + l0 + ll;
        out[idx] = x[idx] + sy[ch][ll];
    }
}

// ---------------- launch ----------------
extern "C" void kernel_launch(void* const* d_in, const int* in_sizes, int n_in,
                              void* d_out, int out_size) {
    const float* x          = (const float*)d_in[0];
    const float* norm_w     = (const float*)d_in[1];
    const float* in_proj_w  = (const float*)d_in[2];
    const float* conv_w     = (const float*)d_in[3];
    const float* conv_b     = (const float*)d_in[4];
    const float* dt_bias    = (const float*)d_in[5];
    const float* A_log      = (const float*)d_in[6];
    const float* Dp         = (const float*)d_in[7];
    const float* gnorm_w    = (const float*)d_in[8];
    const float* out_proj_w = (const float*)d_in[9];
    float* out = (float*)d_out;

    static int smem_set = 0;
    if (!smem_set) {
        cudaFuncSetAttribute(k_intra_mma, cudaFuncAttributeMaxDynamicSharedMemorySize, SMEM_INTRA);
        cudaFuncSetAttribute(k_ycorr, cudaFuncAttributeMaxDynamicSharedMemorySize, SMEM_YCORR);
        smem_set = 1;
    }

    k_rms_scan<<<BATCH * 128, 256>>>(x, norm_w);
    k_inproj_mma<<<dim3(6, MROWS / 128), 256>>>(in_proj_w);
    k_dt<<<BB * NC, CHUNK>>>(dt_bias, A_log);
    k_conv<<<MROWS / 4, 448>>>(conv_w, conv_b);
    k_intra_mma<<<BB * NC * NH * 4, 128, SMEM_INTRA>>>();
    k_states<<<BB * NC * NH, 256>>>();
    k_recur<<<BB * NH * 8, 256>>>();
    k_ycorr<<<BB * NC * NH, 128, SMEM_YCORR>>>(Dp);
    k_gate<<<MROWS, DIN>>>(gnorm_w);
    k_outproj<<<MROWS / 128, 256>>>(out_proj_w);
    k_unscan<<<BATCH * 128, 256>>>(x, out);
}

// round 4
// speedup vs baseline: 1.9425x; 1.1098x over previous
#include <cuda_runtime.h>
#include <cuda_bf16.h>
#include <math.h>
#include <stdint.h>

// ---------------- problem constants ----------------
#define BATCH   2
#define CMODEL  96
#define LSEQ    4096
#define BB      8
#define DIN     192
#define DSTATE  128
#define CONVD   448
#define NH      3
#define HD      64
#define NPROJ   643
#define NPROJ_S 644             // padded stride (16B-aligned rows)
#define CHUNK   256
#define NC      16
#define MROWS   (BB*LSEQ)       // 32768

// ---------------- scratch ----------------
__device__ float g_xs[MROWS * CMODEL];
__device__ float g_zxbcdt[MROWS * NPROJ_S];
__device__ float g_xBC[MROWS * CONVD];
__device__ float g_dt[MROWS * NH];
__device__ float g_dAc[MROWS * NH];
__device__ float g_y[MROWS * DIN];
__device__ float g_yn[MROWS * DIN];
__device__ float g_ysd[MROWS * CMODEL];
__device__ float g_states[BB * NC * NH * HD * DSTATE];
__device__ float g_prev[BB * NC * NH * HD * DSTATE];

// ---------------- mma helpers ----------------
__device__ __forceinline__ uint32_t f2tf(float f) {
    uint32_t u;
    asm("cvt.rna.tf32.f32 %0, %1;" : "=r"(u) : "f"(f));
    return u;
}
__device__ __forceinline__ void mma_tf32(float c[4], uint32_t a0, uint32_t a1, uint32_t a2, uint32_t a3,
                                         uint32_t b0, uint32_t b1) {
    asm volatile("mma.sync.aligned.m16n8k8.row.col.f32.tf32.tf32.f32 "
                 "{%0,%1,%2,%3}, {%4,%5,%6,%7}, {%8,%9}, {%0,%1,%2,%3};"
                 : "+f"(c[0]), "+f"(c[1]), "+f"(c[2]), "+f"(c[3])
                 : "r"(a0), "r"(a1), "r"(a2), "r"(a3), "r"(b0), "r"(b1));
}

// ============ kernel 1: rmsnorm + cross-scan, tiled & coalesced ============
__global__ void k_rms_scan(const float* __restrict__ x, const float* __restrict__ norm_w) {
    __shared__ float sx[96][33];
    __shared__ float rs[32];
    __shared__ float wsh[96];
    int bi = blockIdx.x >> 7;
    int l0 = (blockIdx.x & 127) * 32;
    int tid = threadIdx.x;                 // 256
    if (tid < 96) wsh[tid] = norm_w[tid];
    for (int i = tid; i < 96 * 32; i += 256) {
        int ch = i >> 5, ll = i & 31;
        sx[ch][ll] = x[((bi * 96 + ch) << 12) + l0 + ll];
    }
    __syncthreads();
    if (tid < 32) {
        float ssum = 0.f;
        #pragma unroll 8
        for (int ch = 0; ch < 96; ch++) { float v = sx[ch][tid]; ssum = fmaf(v, v, ssum); }
        rs[tid] = rsqrtf(ssum / 96.0f + 1.1920929e-07f);
    }
    __syncthreads();
    for (int i = tid; i < 3072; i += 256) {
        int ll = i / 96, ch = i - ll * 96;
        int l = l0 + ll;
        float nv = sx[ch][ll] * rs[ll] * wsh[ch];
        int hh = l >> 6, ww = l & 63;
        int lt = (ww << 6) + hh;
        g_xs[(((bi * 4 + 0) << 12) + l) * 96 + ch] = nv;
        g_xs[(((bi * 4 + 1) << 12) + (4095 - l)) * 96 + ch] = nv;
        g_xs[(((bi * 4 + 2) << 12) + lt) * 96 + ch] = nv;
        g_xs[(((bi * 4 + 3) << 12) + (4095 - lt)) * 96 + ch] = nv;
    }
}

// ============ kernel 2: in_proj GEMM via tf32 MMA (M=32768, N=643, K=96) ============
__global__ void k_inproj_mma(const float* __restrict__ W) {
    __shared__ uint32_t As[128][36];
    __shared__ uint32_t Bs[128][36];
    int bm = blockIdx.y * 128;
    int bn = blockIdx.x * 128;
    int tid = threadIdx.x;
    int lane = tid & 31, wid = tid >> 5;
    int wm = (wid & 1) * 64;
    int wn = (wid >> 1) * 32;
    float acc[4][4][4] = {};
    for (int kk = 0; kk < 96; kk += 32) {
        for (int i = tid; i < 128 * 8; i += 256) {
            int r = i >> 3, c = (i & 7) * 4;
            float4 v = *(const float4*)&g_xs[(bm + r) * CMODEL + kk + c];
            As[r][c + 0] = f2tf(v.x); As[r][c + 1] = f2tf(v.y);
            As[r][c + 2] = f2tf(v.z); As[r][c + 3] = f2tf(v.w);
        }
        for (int i = tid; i < 128 * 8; i += 256) {
            int r = i >> 3, c = (i & 7) * 4;
            int n = bn + r;
            float4 v = make_float4(0.f, 0.f, 0.f, 0.f);
            if (n < NPROJ) v = *(const float4*)&W[n * CMODEL + kk + c];
            Bs[r][c + 0] = f2tf(v.x); Bs[r][c + 1] = f2tf(v.y);
            Bs[r][c + 2] = f2tf(v.z); Bs[r][c + 3] = f2tf(v.w);
        }
        __syncthreads();
        #pragma unroll
        for (int k8 = 0; k8 < 32; k8 += 8) {
            uint32_t af[4][4], bf[4][2];
            int rA = lane >> 2, kA = k8 + (lane & 3);
            #pragma unroll
            for (int mi = 0; mi < 4; mi++) {
                int r = wm + mi * 16 + rA;
                af[mi][0] = As[r][kA];     af[mi][1] = As[r + 8][kA];
                af[mi][2] = As[r][kA + 4]; af[mi][3] = As[r + 8][kA + 4];
            }
            #pragma unroll
            for (int ni = 0; ni < 4; ni++) {
                int cn = wn + ni * 8 + (lane >> 2);
                bf[ni][0] = Bs[cn][kA];
                bf[ni][1] = Bs[cn][kA + 4];
            }
            #pragma unroll
            for (int mi = 0; mi < 4; mi++)
                #pragma unroll
                for (int ni = 0; ni < 4; ni++)
                    mma_tf32(acc[mi][ni], af[mi][0], af[mi][1], af[mi][2], af[mi][3],
                             bf[ni][0], bf[ni][1]);
        }
        __syncthreads();
    }
    int gid = lane >> 2, tig = lane & 3;
    #pragma unroll
    for (int mi = 0; mi < 4; mi++) {
        int r0 = bm + wm + mi * 16 + gid;
        #pragma unroll
        for (int ni = 0; ni < 4; ni++) {
            int c0 = bn + wn + ni * 8 + tig * 2;
            if (c0 < NPROJ) {
                g_zxbcdt[r0 * NPROJ_S + c0]       = acc[mi][ni][0];
                g_zxbcdt[(r0 + 8) * NPROJ_S + c0] = acc[mi][ni][2];
            }
            if (c0 + 1 < NPROJ) {
                g_zxbcdt[r0 * NPROJ_S + c0 + 1]       = acc[mi][ni][1];
                g_zxbcdt[(r0 + 8) * NPROJ_S + c0 + 1] = acc[mi][ni][3];
            }
        }
    }
}

// ============ kernel 3: dt softplus + per-chunk cumsum via warp scan ============
__global__ void k_dt(const float* __restrict__ dt_bias, const float* __restrict__ A_log) {
    int cb = blockIdx.x;
    int t  = threadIdx.x;                 // 256
    int m  = cb * CHUNK + t;
    int lane = t & 31, wid = t >> 5;
    __shared__ float wsum[8], woff[8];
    for (int h = 0; h < NH; h++) {
        float raw = g_zxbcdt[m * NPROJ_S + (DIN + CONVD) + h] + dt_bias[h];
        float dtv = (raw > 20.0f) ? raw : log1pf(expf(raw));
        g_dt[m * NH + h] = dtv;
        float Ah = -expf(A_log[h]);
        float s = dtv * Ah;
        #pragma unroll
        for (int o = 1; o < 32; o <<= 1) {
            float n = __shfl_up_sync(0xffffffffu, s, o);
            if (lane >= o) s += n;
        }
        if (lane == 31) wsum[wid] = s;
        __syncthreads();
        if (t < 8) {
            float ws = wsum[t];
            #pragma unroll
            for (int o = 1; o < 8; o <<= 1) {
                float n = __shfl_up_sync(0xffu, ws, o);
                if (t >= o) ws += n;
            }
            woff[t] = ws;
        }
        __syncthreads();
        float off = wid ? woff[wid - 1] : 0.0f;
        g_dAc[m * NH + h] = s + off;
        __syncthreads();
    }
}

// ============ kernel 4: depthwise causal conv + SiLU, sliding window ============
// thread = (channel-quad, row-group of 8); 224 threads = 112 quads x 2 rowgroups
__global__ void k_conv(const float* __restrict__ cw, const float* __restrict__ cb) {
    int tid = threadIdx.x;
    int q = tid % 112, rg = tid / 112;
    int c4 = q * 4;
    int base = (blockIdx.x * 2 + rg) * 8;
    float4 r0 = *(const float4*)&cw[(c4 + 0) * 4];
    float4 r1 = *(const float4*)&cw[(c4 + 1) * 4];
    float4 r2 = *(const float4*)&cw[(c4 + 2) * 4];
    float4 r3 = *(const float4*)&cw[(c4 + 3) * 4];
    float4 bias = *(const float4*)&cb[c4];
    const float* src = g_zxbcdt + DIN + c4;
    bool seqstart = ((base & 4095) == 0);
    float4 vm3, vm2, vm1;
    if (seqstart) {
        vm3 = make_float4(0.f, 0.f, 0.f, 0.f);
        vm2 = vm3; vm1 = vm3;
    } else {
        vm3 = *(const float4*)&src[(base - 3) * NPROJ_S];
        vm2 = *(const float4*)&src[(base - 2) * NPROJ_S];
        vm1 = *(const float4*)&src[(base - 1) * NPROJ_S];
    }
    #pragma unroll
    for (int i = 0; i < 8; i++) {
        float4 vc = *(const float4*)&src[(base + i) * NPROJ_S];
        float4 a;
        a.x = bias.x + r0.x * vm3.x + r0.y * vm2.x + r0.z * vm1.x + r0.w * vc.x;
        a.y = bias.y + r1.x * vm3.y + r1.y * vm2.y + r1.z * vm1.y + r1.w * vc.y;
        a.z = bias.z + r2.x * vm3.z + r2.y * vm2.z + r2.z * vm1.z + r2.w * vc.z;
        a.w = bias.w + r3.x * vm3.w + r3.y * vm2.w + r3.z * vm1.w + r3.w * vc.w;
        float4 o;
        o.x = a.x / (1.0f + expf(-a.x));
        o.y = a.y / (1.0f + expf(-a.y));
        o.z = a.z / (1.0f + expf(-a.z));
        o.w = a.w / (1.0f + expf(-a.w));
        *(float4*)&g_xBC[(base + i) * CONVD + c4] = o;
        vm3 = vm2; vm2 = vm1; vm1 = vc;
    }
}

// ============ kernel 5: intra-chunk SSD via tf32 MMA ============
__global__ void k_intra_mma() {
    extern __shared__ uint32_t smb[];
    uint32_t (*Cs)[132]  = (uint32_t(*)[132])smb;
    uint32_t (*Bs)[132]  = (uint32_t(*)[132])(smb + 64 * 132);
    uint32_t (*Xs)[68]   = (uint32_t(*)[68]) (smb + 2 * 64 * 132);
    uint32_t (*Ssm)[68]  = (uint32_t(*)[68]) (smb + 2 * 64 * 132 + 64 * 68);
    float* dAs = (float*)(smb + 2 * 64 * 132 + 2 * 64 * 68);
    float* dAt = dAs + 64;
    float* dtt = dAt + 64;

    int bx = blockIdx.x;
    int st = bx & 3;
    int rest = bx >> 2;
    int h = rest % 3; rest /= 3;
    int c = rest & 15;
    int bb = rest >> 4;
    int m0 = bb * LSEQ + c * CHUNK;
    int tid = threadIdx.x, lane = tid & 31, wid = tid >> 5;

    int sbase = m0 + st * 64;
    for (int i = tid; i < 64 * 32; i += 128) {
        int r = i >> 5, c4 = (i & 31) * 4;
        float4 v = *(const float4*)&g_xBC[(sbase + r) * CONVD + (DIN + DSTATE) + c4];
        Cs[r][c4 + 0] = f2tf(v.x); Cs[r][c4 + 1] = f2tf(v.y);
        Cs[r][c4 + 2] = f2tf(v.z); Cs[r][c4 + 3] = f2tf(v.w);
    }
    if (tid < 64) dAs[tid] = g_dAc[(sbase + tid) * NH + h];

    float accY[8][4] = {};

    for (int tt = 0; tt <= st; tt++) {
        int tbase = m0 + tt * 64;
        __syncthreads();
        for (int i = tid; i < 64 * 32; i += 128) {
            int r = i >> 5, c4 = (i & 31) * 4;
            float4 v = *(const float4*)&g_xBC[(tbase + r) * CONVD + DIN + c4];
            Bs[r][c4 + 0] = f2tf(v.x); Bs[r][c4 + 1] = f2tf(v.y);
            Bs[r][c4 + 2] = f2tf(v.z); Bs[r][c4 + 3] = f2tf(v.w);
        }
        for (int i = tid; i < 64 * 16; i += 128) {
            int r = i >> 4, c4 = (i & 15) * 4;
            float4 v = *(const float4*)&g_xBC[(tbase + r) * CONVD + h * HD + c4];
            Xs[r][c4 + 0] = f2tf(v.x); Xs[r][c4 + 1] = f2tf(v.y);
            Xs[r][c4 + 2] = f2tf(v.z); Xs[r][c4 + 3] = f2tf(v.w);
        }
        if (tid < 64) {
            dAt[tid] = g_dAc[(tbase + tid) * NH + h];
            dtt[tid] = g_dt[(tbase + tid) * NH + h];
        }
        __syncthreads();

        float S[8][4] = {};
        #pragma unroll
        for (int k8 = 0; k8 < 128; k8 += 8) {
            int rA = wid * 16 + (lane >> 2), kA = k8 + (lane & 3);
            uint32_t a0 = Cs[rA][kA], a1 = Cs[rA + 8][kA];
            uint32_t a2 = Cs[rA][kA + 4], a3 = Cs[rA + 8][kA + 4];
            #pragma unroll
            for (int nf = 0; nf < 8; nf++) {
                int t = nf * 8 + (lane >> 2);
                mma_tf32(S[nf], a0, a1, a2, a3, Bs[t][kA], Bs[t][kA + 4]);
            }
        }
        {
            int gid = lane >> 2, tig = lane & 3;
            #pragma unroll
            for (int nf = 0; nf < 8; nf++) {
                #pragma unroll
                for (int e = 0; e < 4; e++) {
                    int sl = wid * 16 + gid + ((e >= 2) ? 8 : 0);
                    int tl = nf * 8 + tig * 2 + (e & 1);
                    bool ok = (tt < st) || (tl <= sl);
                    float f = ok ? __expf(dAs[sl] - dAt[tl]) * dtt[tl] : 0.0f;
                    Ssm[sl][tl] = f2tf(S[nf][e] * f);
                }
            }
        }
        __syncthreads();
        #pragma unroll
        for (int k8 = 0; k8 < 64; k8 += 8) {
            int rA = wid * 16 + (lane >> 2), kA = k8 + (lane & 3);
            uint32_t a0 = Ssm[rA][kA], a1 = Ssm[rA + 8][kA];
            uint32_t a2 = Ssm[rA][kA + 4], a3 = Ssm[rA + 8][kA + 4];
            #pragma unroll
            for (int nf = 0; nf < 8; nf++) {
                int p = nf * 8 + (lane >> 2);
                mma_tf32(accY[nf], a0, a1, a2, a3, Xs[kA][p], Xs[kA + 4][p]);
            }
        }
    }
    int gid = lane >> 2, tig = lane & 3;
    #pragma unroll
    for (int nf = 0; nf < 8; nf++) {
        int s = st * 64 + wid * 16 + gid;
        int p = nf * 8 + tig * 2;
        g_y[(m0 + s) * DIN + h * HD + p]           = accY[nf][0];
        g_y[(m0 + s) * DIN + h * HD + p + 1]       = accY[nf][1];
        g_y[(m0 + s + 8) * DIN + h * HD + p]       = accY[nf][2];
        g_y[(m0 + s + 8) * DIN + h * HD + p + 1]   = accY[nf][3];
    }
}
#define SMEM_INTRA ((2 * 64 * 132 + 2 * 64 * 68 + 3 * 64) * 4)

// ============ kernel 6: per-chunk end states via tf32 MMA ============
__global__ void k_states() {
    __shared__ uint32_t Xs[32][72];
    __shared__ uint32_t Bw[32][136];
    __shared__ float wts[32];
    int bx = blockIdx.x;
    int h = bx % 3; int rest = bx / 3;
    int c = rest & 15; int bb = rest >> 4;
    int m0 = bb * LSEQ + c * CHUNK;
    int tid = threadIdx.x, lane = tid & 31, wid = tid >> 5;   // 256 thr / 8 warps
    int wm = (wid & 3) * 16;
    int wn = (wid >> 2) * 64;
    float dAl = g_dAc[(m0 + 255) * NH + h];
    float acc[8][4] = {};
    for (int tc = 0; tc < CHUNK; tc += 32) {
        __syncthreads();
        if (tid < 32) {
            int t = tc + tid;
            wts[tid] = expf(dAl - g_dAc[(m0 + t) * NH + h]) * g_dt[(m0 + t) * NH + h];
        }
        __syncthreads();
        for (int i = tid; i < 32 * 16; i += 256) {
            int r = i >> 4, c4 = (i & 15) * 4;
            float4 v = *(const float4*)&g_xBC[(m0 + tc + r) * CONVD + h * HD + c4];
            Xs[r][c4 + 0] = f2tf(v.x); Xs[r][c4 + 1] = f2tf(v.y);
            Xs[r][c4 + 2] = f2tf(v.z); Xs[r][c4 + 3] = f2tf(v.w);
        }
        for (int i = tid; i < 32 * 32; i += 256) {
            int r = i >> 5, c4 = (i & 31) * 4;
            float w = wts[r];
            float4 v = *(const float4*)&g_xBC[(m0 + tc + r) * CONVD + DIN + c4];
            Bw[r][c4 + 0] = f2tf(w * v.x); Bw[r][c4 + 1] = f2tf(w * v.y);
            Bw[r][c4 + 2] = f2tf(w * v.z); Bw[r][c4 + 3] = f2tf(w * v.w);
        }
        __syncthreads();
        #pragma unroll
        for (int k8 = 0; k8 < 32; k8 += 8) {
            int rA = wm + (lane >> 2), kA = k8 + (lane & 3);
            uint32_t a0 = Xs[kA][rA],     a1 = Xs[kA][rA + 8];
            uint32_t a2 = Xs[kA + 4][rA], a3 = Xs[kA + 4][rA + 8];
            #pragma unroll
            for (int ni = 0; ni < 8; ni++) {
                int cn = wn + ni * 8 + (lane >> 2);
                mma_tf32(acc[ni], a0, a1, a2, a3, Bw[kA][cn], Bw[kA + 4][cn]);
            }
        }
    }
    int blk = (bb * 16 + c) * 3 + h;
    int gid = lane >> 2, tig = lane & 3;
    #pragma unroll
    for (int ni = 0; ni < 8; ni++) {
        int p0 = wm + gid;
        int n0 = wn + ni * 8 + tig * 2;
        float* dst = &g_states[blk * (HD * DSTATE)];
        dst[p0 * DSTATE + n0]           = acc[ni][0];
        dst[p0 * DSTATE + n0 + 1]       = acc[ni][1];
        dst[(p0 + 8) * DSTATE + n0]     = acc[ni][2];
        dst[(p0 + 8) * DSTATE + n0 + 1] = acc[ni][3];
    }
}

// ============ kernel 7: inter-chunk recurrence (192 blocks) ============
__global__ void k_recur() {
    int bxs = blockIdx.x;          // 192
    int slice = bxs & 7;
    int bh = bxs >> 3;
    int bb = bh / 3, h = bh % 3;
    int tid = threadIdx.x;         // 256
    float hr[4] = {0.f, 0.f, 0.f, 0.f};
    for (int c = 0; c < NC; c++) {
        int blk = (bb * 16 + c) * 3 + h;
        float decay = expf(g_dAc[(bb * LSEQ + c * CHUNK + 255) * NH + h]);
        #pragma unroll
        for (int r = 0; r < 4; r++) {
            int idx = blk * (HD * DSTATE) + slice * 1024 + r * 256 + tid;
            g_prev[idx] = hr[r];
            hr[r] = fmaf(decay, hr[r], g_states[idx]);
        }
    }
}

// ============ kernel 8: inter-chunk y correction via tf32 MMA + D*x ============
__global__ void k_ycorr(const float* __restrict__ Dp) {
    extern __shared__ uint32_t ysm[];
    uint32_t (*prevS)[132] = (uint32_t(*)[132])ysm;
    uint32_t (*Cs)[132]    = (uint32_t(*)[132])(ysm + 64 * 132);
    float* exps            = (float*)(ysm + 2 * 64 * 132);
    int bx = blockIdx.x;
    int h = bx % 3; int rest = bx / 3;
    int c = rest & 15; int bb = rest >> 4;
    int m0 = bb * LSEQ + c * CHUNK;
    int blk = (bb * 16 + c) * 3 + h;
    int tid = threadIdx.x, lane = tid & 31, wid = tid >> 5;   // 128 thr / 4 warps
    float Dh = Dp[h];
    for (int i = tid; i < 64 * 32; i += 128) {
        int p = i >> 5, c4 = (i & 31) * 4;
        float4 v = *(const float4*)&g_prev[blk * (HD * DSTATE) + p * DSTATE + c4];
        prevS[p][c4 + 0] = f2tf(v.x); prevS[p][c4 + 1] = f2tf(v.y);
        prevS[p][c4 + 2] = f2tf(v.z); prevS[p][c4 + 3] = f2tf(v.w);
    }
    int gid = lane >> 2, tig = lane & 3;
    for (int stile = 0; stile < 4; stile++) {
        __syncthreads();
        for (int i = tid; i < 64 * 32; i += 128) {
            int r = i >> 5, c4 = (i & 31) * 4;
            float4 v = *(const float4*)&g_xBC[(m0 + stile * 64 + r) * CONVD + (DIN + DSTATE) + c4];
            Cs[r][c4 + 0] = f2tf(v.x); Cs[r][c4 + 1] = f2tf(v.y);
            Cs[r][c4 + 2] = f2tf(v.z); Cs[r][c4 + 3] = f2tf(v.w);
        }
        if (tid < 64) exps[tid] = expf(g_dAc[(m0 + stile * 64 + tid) * NH + h]);
        __syncthreads();
        float acc[8][4] = {};
        #pragma unroll
        for (int k8 = 0; k8 < 128; k8 += 8) {
            int rA = wid * 16 + gid, kA = k8 + (lane & 3);
            uint32_t a0 = Cs[rA][kA],     a1 = Cs[rA + 8][kA];
            uint32_t a2 = Cs[rA][kA + 4], a3 = Cs[rA + 8][kA + 4];
            #pragma unroll
            for (int ni = 0; ni < 8; ni++) {
                int cn = ni * 8 + gid;
                mma_tf32(acc[ni], a0, a1, a2, a3, prevS[cn][kA], prevS[cn][kA + 4]);
            }
        }
        #pragma unroll
        for (int ni = 0; ni < 8; ni++) {
            int p = ni * 8 + tig * 2;
            int s0 = wid * 16 + gid;
            int m1 = m0 + stile * 64 + s0;
            int m2 = m1 + 8;
            float eA1 = exps[s0], eA2 = exps[s0 + 8];
            float xv10 = g_xBC[m1 * CONVD + h * HD + p];
            float xv11 = g_xBC[m1 * CONVD + h * HD + p + 1];
            float xv20 = g_xBC[m2 * CONVD + h * HD + p];
            float xv21 = g_xBC[m2 * CONVD + h * HD + p + 1];
            g_y[m1 * DIN + h * HD + p]     += eA1 * acc[ni][0] + Dh * xv10;
            g_y[m1 * DIN + h * HD + p + 1] += eA1 * acc[ni][1] + Dh * xv11;
            g_y[m2 * DIN + h * HD + p]     += eA2 * acc[ni][2] + Dh * xv20;
            g_y[m2 * DIN + h * HD + p + 1] += eA2 * acc[ni][3] + Dh * xv21;
        }
    }
}
#define SMEM_YCORR ((2 * 64 * 132) * 4 + 64 * 4)

// ============ kernel 9: gating + rmsnorm, warp-per-row ============
__global__ void k_gate(const float* __restrict__ gw) {
    int wid = threadIdx.x >> 5, lane = threadIdx.x & 31;   // 256 thr = 8 warps
    int row0 = blockIdx.x * 32 + wid * 4;
    #pragma unroll
    for (int rr = 0; rr < 4; rr++) {
        int m = row0 + rr;
        float2 vv[3];
        float ss = 0.f;
        #pragma unroll
        for (int j = 0; j < 3; j++) {
            int col = (j * 32 + lane) * 2;
            float2 y2 = *(const float2*)&g_y[m * DIN + col];
            float2 z2 = *(const float2*)&g_zxbcdt[m * NPROJ_S + col];
            float vx = y2.x * (z2.x / (1.0f + expf(-z2.x)));
            float vy = y2.y * (z2.y / (1.0f + expf(-z2.y)));
            vv[j] = make_float2(vx, vy);
            ss = fmaf(vx, vx, fmaf(vy, vy, ss));
        }
        #pragma unroll
        for (int o = 16; o > 0; o >>= 1) ss += __shfl_xor_sync(0xffffffffu, ss, o);
        float r = rsqrtf(ss / 192.0f + 1e-5f);
        #pragma unroll
        for (int j = 0; j < 3; j++) {
            int col = (j * 32 + lane) * 2;
            float2 o2;
            o2.x = vv[j].x * r * gw[col];
            o2.y = vv[j].y * r * gw[col + 1];
            *(float2*)&g_yn[m * DIN + col] = o2;
        }
    }
}

// ============ kernel 10: out_proj GEMM via tf32 MMA (M=32768, N=96, K=192) ============
__global__ void k_outproj(const float* __restrict__ W) {
    __shared__ uint32_t As[128][36];
    __shared__ uint32_t Bs[96][36];
    int bm = blockIdx.x * 128;
    int tid = threadIdx.x, lane = tid & 31, wid = tid >> 5;   // 256 thr / 8 warps
    int wm = (wid & 3) * 32;
    int wn = (wid >> 2) * 48;
    float acc[2][6][4] = {};
    for (int kk = 0; kk < 192; kk += 32) {
        for (int i = tid; i < 128 * 8; i += 256) {
            int r = i >> 3, c4 = (i & 7) * 4;
            float4 v = *(const float4*)&g_yn[(bm + r) * DIN + kk + c4];
            As[r][c4 + 0] = f2tf(v.x); As[r][c4 + 1] = f2tf(v.y);
            As[r][c4 + 2] = f2tf(v.z); As[r][c4 + 3] = f2tf(v.w);
        }
        for (int i = tid; i < 96 * 8; i += 256) {
            int r = i >> 3, c4 = (i & 7) * 4;
            float4 v = *(const float4*)&W[r * DIN + kk + c4];
            Bs[r][c4 + 0] = f2tf(v.x); Bs[r][c4 + 1] = f2tf(v.y);
            Bs[r][c4 + 2] = f2tf(v.z); Bs[r][c4 + 3] = f2tf(v.w);
        }
        __syncthreads();
        #pragma unroll
        for (int k8 = 0; k8 < 32; k8 += 8) {
            int kA = k8 + (lane & 3);
            uint32_t af[2][4];
            #pragma unroll
            for (int mi = 0; mi < 2; mi++) {
                int r = wm + mi * 16 + (lane >> 2);
                af[mi][0] = As[r][kA];     af[mi][1] = As[r + 8][kA];
                af[mi][2] = As[r][kA + 4]; af[mi][3] = As[r + 8][kA + 4];
            }
            #pragma unroll
            for (int ni = 0; ni < 6; ni++) {
                int cn = wn + ni * 8 + (lane >> 2);
                uint32_t b0 = Bs[cn][kA], b1 = Bs[cn][kA + 4];
                #pragma unroll
                for (int mi = 0; mi < 2; mi++)
                    mma_tf32(acc[mi][ni], af[mi][0], af[mi][1], af[mi][2], af[mi][3], b0, b1);
            }
        }
        __syncthreads();
    }
    int gid = lane >> 2, tig = lane & 3;
    #pragma unroll
    for (int mi = 0; mi < 2; mi++) {
        int r0 = bm + wm + mi * 16 + gid;
        #pragma unroll
        for (int ni = 0; ni < 6; ni++) {
            int c0 = wn + ni * 8 + tig * 2;
            g_ysd[r0 * CMODEL + c0]           = acc[mi][ni][0];
            g_ysd[r0 * CMODEL + c0 + 1]       = acc[mi][ni][1];
            g_ysd[(r0 + 8) * CMODEL + c0]     = acc[mi][ni][2];
            g_ysd[(r0 + 8) * CMODEL + c0 + 1] = acc[mi][ni][3];
        }
    }
}

// ============ kernel 11: un-scan + residual, tiled & coalesced ============
__global__ void k_unscan(const float* __restrict__ x, float* __restrict__ out) {
    __shared__ float sy[96][33];
    int bi = blockIdx.x >> 7;
    int l0 = (blockIdx.x & 127) * 32;
    int tid = threadIdx.x;                 // 256
    for (int i = tid; i < 3072; i += 256) {
        int ll = i / 96, ch = i - ll * 96;
        int l = l0 + ll;
        int hh = l >> 6, ww = l & 63;
        int lt = (ww << 6) + hh;
        float v = g_ysd[(((bi * 4 + 0) << 12) + l) * 96 + ch]
                + g_ysd[(((bi * 4 + 1) << 12) + (4095 - l)) * 96 + ch]
                + g_ysd[(((bi * 4 + 2) << 12) + lt) * 96 + ch]
                + g_ysd[(((bi * 4 + 3) << 12) + (4095 - lt)) * 96 + ch];
        sy[ch][ll] = 0.25f * v;
    }
    __syncthreads();
    for (int i = tid; i < 96 * 32; i += 256) {
        int ch = i >> 5, ll = i & 31;
        int idx = ((bi * 96 + ch) << 12) + l0 + ll;
        out[idx] = x[idx] + sy[ch][ll];
    }
}

// ---------------- launch ----------------
extern "C" void kernel_launch(void* const* d_in, const int* in_sizes, int n_in,
                              void* d_out, int out_size) {
    const float* x          = (const float*)d_in[0];
    const float* norm_w     = (const float*)d_in[1];
    const float* in_proj_w  = (const float*)d_in[2];
    const float* conv_w     = (const float*)d_in[3];
    const float* conv_b     = (const float*)d_in[4];
    const float* dt_bias    = (const float*)d_in[5];
    const float* A_log      = (const float*)d_in[6];
    const float* Dp         = (const float*)d_in[7];
    const float* gnorm_w    = (const float*)d_in[8];
    const float* out_proj_w = (const float*)d_in[9];
    float* out = (float*)d_out;

    static int smem_set = 0;
    if (!smem_set) {
        cudaFuncSetAttribute(k_intra_mma, cudaFuncAttributeMaxDynamicSharedMemorySize, SMEM_INTRA);
        cudaFuncSetAttribute(k_ycorr, cudaFuncAttributeMaxDynamicSharedMemorySize, SMEM_YCORR);
        smem_set = 1;
    }

    k_rms_scan<<<BATCH * 128, 256>>>(x, norm_w);
    k_inproj_mma<<<dim3(6, MROWS / 128), 256>>>(in_proj_w);
    k_dt<<<BB * NC, CHUNK>>>(dt_bias, A_log);
    k_conv<<<MROWS / 16, 224>>>(conv_w, conv_b);
    k_intra_mma<<<BB * NC * NH * 4, 128, SMEM_INTRA>>>();
    k_states<<<BB * NC * NH, 256>>>();
    k_recur<<<BB * NH * 8, 256>>>();
    k_ycorr<<<BB * NC * NH, 128, SMEM_YCORR>>>(Dp);
    k_gate<<<MROWS / 32, 256>>>(gnorm_w);
    k_outproj<<<MROWS / 128, 256>>>(out_proj_w);
    k_unscan<<<BATCH * 128, 256>>>(x, out);
}